// round 1
// baseline (speedup 1.0000x reference)
#include <cuda_runtime.h>

#define Nn 4
#define Cc 128
#define Hh 256
#define Ww 256
#define HW (Hh*Ww)

// Scratch (allocation-free: module-scope device globals)
__device__ float g_dk[(size_t)Nn*9*HW];        // 9.4 MB  dyn kernels (L1-normalized)
__device__ float g_cat[(size_t)Nn*2*Cc*HW];    // 268 MB  [dyn_ms ; fix_ms]
__device__ float g_fused[(size_t)Nn*Cc*HW];    // 134 MB  refine output

// ---------------------------------------------------------------------------
// K1: dyn_kernel = conv(ms, dyn_w[9,128,3,3]) + b, then L1-normalize over 9 taps
// block = 128 px of one row; loop over 128 input channels with smem tiles.
// ---------------------------------------------------------------------------
__global__ __launch_bounds__(128) void k1_dynkernel(
    const float* __restrict__ ms,
    const float* __restrict__ dyn_w,
    const float* __restrict__ dyn_b)
{
    const int w0 = blockIdx.x * 128;
    const int h  = blockIdx.y;
    const int n  = blockIdx.z;
    const int tid = threadIdx.x;

    __shared__ float Xs[3][130];
    __shared__ float Wsm[9][9];

    float acc[9];
#pragma unroll
    for (int k = 0; k < 9; k++) acc[k] = dyn_b[k];

    for (int ic = 0; ic < Cc; ic++) {
        const float* mp = ms + ((size_t)(n*Cc + ic))*HW;
        for (int idx = tid; idx < 3*130; idx += 128) {
            int r = idx / 130, cc2 = idx % 130;
            int hh = h + r - 1, ww = w0 + cc2 - 1;
            float v = 0.f;
            if (hh >= 0 && hh < Hh && ww >= 0 && ww < Ww) v = mp[hh*Ww + ww];
            Xs[r][cc2] = v;
        }
        if (tid < 81)
            Wsm[tid/9][tid%9] = dyn_w[(tid/9)*(Cc*9) + ic*9 + (tid%9)];
        __syncthreads();

#pragma unroll
        for (int tap = 0; tap < 9; tap++) {
            float xv = Xs[tap/3][tid + (tap%3)];
#pragma unroll
            for (int k = 0; k < 9; k++) acc[k] += Wsm[k][tap] * xv;
        }
        __syncthreads();
    }

    float denom = 0.f;
#pragma unroll
    for (int k = 0; k < 9; k++) denom += fabsf(acc[k]);
    float inv = 1.f / denom;
#pragma unroll
    for (int k = 0; k < 9; k++)
        g_dk[((size_t)(n*9 + k))*HW + (size_t)h*Ww + w0 + tid] = acc[k] * inv;
}

// ---------------------------------------------------------------------------
// K2: build concat tensor. For one (n,c,h) row:
//   fix_ms  = relu(BN1(depthwise3x3(ms)))          -> g_cat[c+128]
//   dyn_ms  = relu(BN2(sum_k dk[k]*patch[k]))      -> g_cat[c]
// Both use the same 3x3 ms patch (loaded once into smem).
// ---------------------------------------------------------------------------
__global__ __launch_bounds__(256) void k2_cat(
    const float* __restrict__ ms,
    const float* __restrict__ fix_w,
    const float* __restrict__ bn1_g, const float* __restrict__ bn1_b,
    const float* __restrict__ bn1_m, const float* __restrict__ bn1_v,
    const float* __restrict__ bn2_g, const float* __restrict__ bn2_b,
    const float* __restrict__ bn2_m, const float* __restrict__ bn2_v)
{
    const int h = blockIdx.x;
    const int c = blockIdx.y;
    const int n = blockIdx.z;
    const int tid = threadIdx.x;

    __shared__ float Xs[3][258];
    __shared__ float Dk[9][256];

    const float* mp = ms + ((size_t)(n*Cc + c))*HW;
    for (int idx = tid; idx < 3*258; idx += 256) {
        int r = idx / 258, cc2 = idx % 258;
        int hh = h + r - 1, ww = cc2 - 1;
        float v = 0.f;
        if (hh >= 0 && hh < Hh && ww >= 0 && ww < Ww) v = mp[hh*Ww + ww];
        Xs[r][cc2] = v;
    }
    for (int idx = tid; idx < 9*256; idx += 256) {
        int k = idx >> 8, w = idx & 255;
        Dk[k][w] = g_dk[((size_t)(n*9 + k))*HW + (size_t)h*Ww + w];
    }
    float s1 = bn1_g[c] * rsqrtf(bn1_v[c] + 1e-5f);
    float t1 = bn1_b[c] - bn1_m[c]*s1;
    float s2 = bn2_g[c] * rsqrtf(bn2_v[c] + 1e-5f);
    float t2 = bn2_b[c] - bn2_m[c]*s2;
    __syncthreads();

    const int w = tid;
    float f = 0.f, d = 0.f;
#pragma unroll
    for (int tap = 0; tap < 9; tap++) {
        float xv = Xs[tap/3][w + (tap%3)];
        f += fix_w[c*9 + tap] * xv;
        d += Dk[tap][w] * xv;
    }
    float dynv = fmaxf(d*s2 + t2, 0.f);
    float fixv = fmaxf(f*s1 + t1, 0.f);
    size_t base = ((size_t)n*2*Cc)*HW + (size_t)h*Ww + w;
    g_cat[base + (size_t)c*HW]        = dynv;
    g_cat[base + (size_t)(Cc + c)*HW] = fixv;
}

// ---------------------------------------------------------------------------
// K3: refine 1x1 conv: fused[oc,p] = refine_b[oc] + sum_k refine_w[oc,k]*cat[k,p]
// GEMM tile: 128 oc x 64 px, KC=16, per thread 8 oc x 4 px, float4 X loads.
// ---------------------------------------------------------------------------
__global__ __launch_bounds__(256) void k3_refine(
    const float* __restrict__ rw,
    const float* __restrict__ rb)
{
    const int p0 = blockIdx.x * 64;
    const int n  = blockIdx.z;
    const int tid = threadIdx.x;
    const int pxg = tid & 15;     // 16 groups of 4 px
    const int ocg = tid >> 4;     // 16 groups of 8 oc

    __shared__ float Xs[16][64];
    __shared__ float Wsh[128][16];

    float acc[8][4];
#pragma unroll
    for (int u = 0; u < 8; u++)
#pragma unroll
        for (int q = 0; q < 4; q++) acc[u][q] = 0.f;

    const float* catn = g_cat + ((size_t)n*2*Cc)*HW;

    for (int k0 = 0; k0 < 2*Cc; k0 += 16) {
        {
            int kk = tid >> 4;
            int j  = (tid & 15) * 4;
            float4 v = *(const float4*)(catn + (size_t)(k0+kk)*HW + p0 + j);
            *(float4*)&Xs[kk][j] = v;
        }
        for (int m = tid; m < 2048; m += 256) {
            int oc = m >> 4, kk = m & 15;
            Wsh[oc][kk] = rw[oc*(2*Cc) + k0 + kk];
        }
        __syncthreads();

#pragma unroll
        for (int kk = 0; kk < 16; kk++) {
            float4 xq = *(const float4*)&Xs[kk][pxg*4];
#pragma unroll
            for (int u = 0; u < 8; u++) {
                float wv = Wsh[ocg*8 + u][kk];
                acc[u][0] += wv*xq.x; acc[u][1] += wv*xq.y;
                acc[u][2] += wv*xq.z; acc[u][3] += wv*xq.w;
            }
        }
        __syncthreads();
    }

#pragma unroll
    for (int u = 0; u < 8; u++) {
        int oc = ocg*8 + u;
        float b = rb[oc];
        float4 o;
        o.x = acc[u][0] + b; o.y = acc[u][1] + b;
        o.z = acc[u][2] + b; o.w = acc[u][3] + b;
        *(float4*)(g_fused + ((size_t)(n*Cc + oc))*HW + p0 + pxg*4) = o;
    }
}

// ---------------------------------------------------------------------------
// K4: joint 3x3 conv (128->128) over p = fused + coef (built in smem load),
// fused sigmoid-gating epilogue: out = fused + p2*(coef - fused).
// Tile: 128 oc x 32 px (one W-segment), KC=8, thread = 4 oc x 4 px.
// ---------------------------------------------------------------------------
#define KC4 8
__global__ __launch_bounds__(256) void k4_joint(
    const float* __restrict__ coef,
    const float* __restrict__ jw,
    const float* __restrict__ jb,
    float* __restrict__ out)
{
    const int w0 = blockIdx.x * 32;
    const int h  = blockIdx.y;
    const int n  = blockIdx.z;
    const int tid = threadIdx.x;
    const int pxg = tid & 7;           // 8 groups * 4 px
    const int ocb = (tid >> 3) * 4;    // 32 groups * 4 oc

    __shared__ float Ps[KC4][3][34];
    __shared__ float Ws2[128*73];      // stride 73 to kill bank conflicts

    float acc[4][4];
#pragma unroll
    for (int u = 0; u < 4; u++)
#pragma unroll
        for (int q = 0; q < 4; q++) acc[u][q] = 0.f;

    const size_t nplane = (size_t)n*Cc*HW;

    for (int ic0 = 0; ic0 < Cc; ic0 += KC4) {
        for (int m = tid; m < KC4*3*34; m += 256) {
            int i = m / 102; int r2 = m % 102;
            int r = r2 / 34; int cc2 = r2 % 34;
            int hh = h + r - 1; int ww = w0 + cc2 - 1;
            float v = 0.f;
            if (hh >= 0 && hh < Hh && ww >= 0 && ww < Ww) {
                size_t idx = nplane + (size_t)(ic0+i)*HW + (size_t)hh*Ww + ww;
                v = g_fused[idx] + coef[idx];
            }
            Ps[i][r][cc2] = v;
        }
        for (int m = tid; m < 128*KC4*9; m += 256) {
            int oc = m / 72; int r = m % 72;
            Ws2[oc*73 + r] = jw[oc*(Cc*9) + ic0*9 + r];
        }
        __syncthreads();

#pragma unroll
        for (int i = 0; i < KC4; i++) {
            float xr[3][6];
#pragma unroll
            for (int r = 0; r < 3; r++)
#pragma unroll
                for (int c2 = 0; c2 < 6; c2++)
                    xr[r][c2] = Ps[i][r][pxg*4 + c2];
#pragma unroll
            for (int u = 0; u < 4; u++) {
                const float* wp = &Ws2[(ocb+u)*73 + i*9];
#pragma unroll
                for (int dy = 0; dy < 3; dy++)
#pragma unroll
                    for (int dx = 0; dx < 3; dx++) {
                        float wv = wp[dy*3 + dx];
#pragma unroll
                        for (int q = 0; q < 4; q++)
                            acc[u][q] += wv * xr[dy][q + dx];
                    }
            }
        }
        __syncthreads();
    }

#pragma unroll
    for (int u = 0; u < 4; u++) {
        int oc = ocb + u;
        float b = jb[oc];
        size_t base = nplane + (size_t)oc*HW + (size_t)h*Ww + w0 + pxg*4;
#pragma unroll
        for (int q = 0; q < 4; q++) {
            float a  = acc[u][q] + b;
            float p2 = 1.f / (1.f + __expf(-a));
            float fu = g_fused[base + q];
            float cf = coef[base + q];
            out[base + q] = fu + p2*(cf - fu);
        }
    }
}

// ---------------------------------------------------------------------------
extern "C" void kernel_launch(void* const* d_in, const int* in_sizes, int n_in,
                              void* d_out, int out_size)
{
    const float* coef  = (const float*)d_in[0];
    const float* ms    = (const float*)d_in[1];
    const float* fix_w = (const float*)d_in[2];
    const float* bn1_g = (const float*)d_in[3];
    const float* bn1_b = (const float*)d_in[4];
    const float* bn1_m = (const float*)d_in[5];
    const float* bn1_v = (const float*)d_in[6];
    const float* dyn_w = (const float*)d_in[7];
    const float* dyn_b = (const float*)d_in[8];
    const float* bn2_g = (const float*)d_in[9];
    const float* bn2_b = (const float*)d_in[10];
    const float* bn2_m = (const float*)d_in[11];
    const float* bn2_v = (const float*)d_in[12];
    const float* refine_w = (const float*)d_in[13];
    const float* refine_b = (const float*)d_in[14];
    const float* joint_w  = (const float*)d_in[15];
    const float* joint_b  = (const float*)d_in[16];
    float* outp = (float*)d_out;

    k1_dynkernel<<<dim3(Ww/128, Hh, Nn), 128>>>(ms, dyn_w, dyn_b);
    k2_cat<<<dim3(Hh, Cc, Nn), 256>>>(ms, fix_w,
                                      bn1_g, bn1_b, bn1_m, bn1_v,
                                      bn2_g, bn2_b, bn2_m, bn2_v);
    k3_refine<<<dim3(HW/64, 1, Nn), 256>>>(refine_w, refine_b);
    k4_joint<<<dim3(Ww/32, Hh, Nn), 256>>>(coef, joint_w, joint_b, outp);
}

// round 3
// speedup vs baseline: 1.5608x; 1.5608x over previous
#include <cuda_runtime.h>
#include <cuda_bf16.h>
#include <cstdint>

#define Nn 4
#define Cc 128
#define Hh 256
#define Ww 256
#define HW (Hh*Ww)

// ---------------- scratch (device globals; allocation-free) ----------------
__device__ float g_dk[(size_t)Nn*9*HW];                      // dyn kernels
__device__ float g_cat[(size_t)Nn*2*Cc*HW];                  // [dyn_ms ; fix_ms]
__device__ float g_fused[(size_t)Nn*Cc*HW];                  // refine output (NCHW)
__device__ __align__(256) __nv_bfloat16 g_phi[(size_t)Nn*HW*Cc];  // p=fused+coef NHWC hi
__device__ __align__(256) __nv_bfloat16 g_plo[(size_t)Nn*HW*Cc];  // p lo
__device__ __align__(256) __nv_bfloat16 g_whi[18*128*64];    // joint W chunks hi
__device__ __align__(256) __nv_bfloat16 g_wlo[18*128*64];    // joint W chunks lo

// ---------------------------------------------------------------------------
// warp-level bf16 MMA (sm_80+ PTX; legal on base compute_103 target)
// ---------------------------------------------------------------------------
__device__ __forceinline__ void mma16816(float* d, const uint32_t* a,
                                         uint32_t b0, uint32_t b1) {
    asm volatile(
        "mma.sync.aligned.m16n8k16.row.col.f32.bf16.bf16.f32 "
        "{%0,%1,%2,%3}, {%4,%5,%6,%7}, {%8,%9}, {%0,%1,%2,%3};"
        : "+f"(d[0]), "+f"(d[1]), "+f"(d[2]), "+f"(d[3])
        : "r"(a[0]), "r"(a[1]), "r"(a[2]), "r"(a[3]), "r"(b0), "r"(b1));
}

// ---------------------------------------------------------------------------
// K1: dyn_kernel conv(ms, dyn_w[9,128,3,3]) + b, L1-normalized over 9 taps
// ---------------------------------------------------------------------------
__global__ __launch_bounds__(128) void k1_dynkernel(
    const float* __restrict__ ms,
    const float* __restrict__ dyn_w,
    const float* __restrict__ dyn_b)
{
    const int w0 = blockIdx.x * 128;
    const int h  = blockIdx.y;
    const int n  = blockIdx.z;
    const int tid = threadIdx.x;

    __shared__ float Xs[3][130];
    __shared__ float Wsm[9][9];

    float acc[9];
#pragma unroll
    for (int k = 0; k < 9; k++) acc[k] = dyn_b[k];

    for (int ic = 0; ic < Cc; ic++) {
        const float* mp = ms + ((size_t)(n*Cc + ic))*HW;
        for (int idx = tid; idx < 3*130; idx += 128) {
            int r = idx / 130, cc2 = idx % 130;
            int hh = h + r - 1, ww = w0 + cc2 - 1;
            float v = 0.f;
            if (hh >= 0 && hh < Hh && ww >= 0 && ww < Ww) v = mp[hh*Ww + ww];
            Xs[r][cc2] = v;
        }
        if (tid < 81)
            Wsm[tid/9][tid%9] = dyn_w[(tid/9)*(Cc*9) + ic*9 + (tid%9)];
        __syncthreads();

#pragma unroll
        for (int tap = 0; tap < 9; tap++) {
            float xv = Xs[tap/3][tid + (tap%3)];
#pragma unroll
            for (int k = 0; k < 9; k++) acc[k] += Wsm[k][tap] * xv;
        }
        __syncthreads();
    }

    float denom = 0.f;
#pragma unroll
    for (int k = 0; k < 9; k++) denom += fabsf(acc[k]);
    float inv = 1.f / denom;
#pragma unroll
    for (int k = 0; k < 9; k++)
        g_dk[((size_t)(n*9 + k))*HW + (size_t)h*Ww + w0 + tid] = acc[k] * inv;
}

// ---------------------------------------------------------------------------
// K2: concat tensor: fix branch + dynamic einsum, shared ms patch
// ---------------------------------------------------------------------------
__global__ __launch_bounds__(256) void k2_cat(
    const float* __restrict__ ms,
    const float* __restrict__ fix_w,
    const float* __restrict__ bn1_g, const float* __restrict__ bn1_b,
    const float* __restrict__ bn1_m, const float* __restrict__ bn1_v,
    const float* __restrict__ bn2_g, const float* __restrict__ bn2_b,
    const float* __restrict__ bn2_m, const float* __restrict__ bn2_v)
{
    const int h = blockIdx.x;
    const int c = blockIdx.y;
    const int n = blockIdx.z;
    const int tid = threadIdx.x;

    __shared__ float Xs[3][258];
    __shared__ float Dk[9][256];

    const float* mp = ms + ((size_t)(n*Cc + c))*HW;
    for (int idx = tid; idx < 3*258; idx += 256) {
        int r = idx / 258, cc2 = idx % 258;
        int hh = h + r - 1, ww = cc2 - 1;
        float v = 0.f;
        if (hh >= 0 && hh < Hh && ww >= 0 && ww < Ww) v = mp[hh*Ww + ww];
        Xs[r][cc2] = v;
    }
    for (int idx = tid; idx < 9*256; idx += 256) {
        int k = idx >> 8, w = idx & 255;
        Dk[k][w] = g_dk[((size_t)(n*9 + k))*HW + (size_t)h*Ww + w];
    }
    float s1 = bn1_g[c] * rsqrtf(bn1_v[c] + 1e-5f);
    float t1 = bn1_b[c] - bn1_m[c]*s1;
    float s2 = bn2_g[c] * rsqrtf(bn2_v[c] + 1e-5f);
    float t2 = bn2_b[c] - bn2_m[c]*s2;
    __syncthreads();

    const int w = tid;
    float f = 0.f, d = 0.f;
#pragma unroll
    for (int tap = 0; tap < 9; tap++) {
        float xv = Xs[tap/3][w + (tap%3)];
        f += fix_w[c*9 + tap] * xv;
        d += Dk[tap][w] * xv;
    }
    float dynv = fmaxf(d*s2 + t2, 0.f);
    float fixv = fmaxf(f*s1 + t1, 0.f);
    size_t base = ((size_t)n*2*Cc)*HW + (size_t)h*Ww + w;
    g_cat[base + (size_t)c*HW]        = dynv;
    g_cat[base + (size_t)(Cc + c)*HW] = fixv;
}

// ---------------------------------------------------------------------------
// K3: refine 1x1 conv, GEMM tile 128 oc x 64 px
// ---------------------------------------------------------------------------
__global__ __launch_bounds__(256) void k3_refine(
    const float* __restrict__ rw,
    const float* __restrict__ rb)
{
    const int p0 = blockIdx.x * 64;
    const int n  = blockIdx.z;
    const int tid = threadIdx.x;
    const int pxg = tid & 15;
    const int ocg = tid >> 4;

    __shared__ float Xs[16][64];
    __shared__ float Wsh[128][16];

    float acc[8][4];
#pragma unroll
    for (int u = 0; u < 8; u++)
#pragma unroll
        for (int q = 0; q < 4; q++) acc[u][q] = 0.f;

    const float* catn = g_cat + ((size_t)n*2*Cc)*HW;

    for (int k0 = 0; k0 < 2*Cc; k0 += 16) {
        {
            int kk = tid >> 4;
            int j  = (tid & 15) * 4;
            float4 v = *(const float4*)(catn + (size_t)(k0+kk)*HW + p0 + j);
            *(float4*)&Xs[kk][j] = v;
        }
        for (int m = tid; m < 2048; m += 256) {
            int oc = m >> 4, kk = m & 15;
            Wsh[oc][kk] = rw[oc*(2*Cc) + k0 + kk];
        }
        __syncthreads();

#pragma unroll
        for (int kk = 0; kk < 16; kk++) {
            float4 xq = *(const float4*)&Xs[kk][pxg*4];
#pragma unroll
            for (int u = 0; u < 8; u++) {
                float wv = Wsh[ocg*8 + u][kk];
                acc[u][0] += wv*xq.x; acc[u][1] += wv*xq.y;
                acc[u][2] += wv*xq.z; acc[u][3] += wv*xq.w;
            }
        }
        __syncthreads();
    }

#pragma unroll
    for (int u = 0; u < 8; u++) {
        int oc = ocg*8 + u;
        float b = rb[oc];
        float4 o;
        o.x = acc[u][0] + b; o.y = acc[u][1] + b;
        o.z = acc[u][2] + b; o.w = acc[u][3] + b;
        *(float4*)(g_fused + ((size_t)(n*Cc + oc))*HW + p0 + pxg*4) = o;
    }
}

// ---------------------------------------------------------------------------
// KW: split joint weights into per-chunk bf16 hi/lo:
//     g_w{hi,lo}[(tap*2+half)*8192 + oc*64 + k] = split(jw[oc, half*64+k, tap])
// ---------------------------------------------------------------------------
__global__ __launch_bounds__(256) void kw_prep(const float* __restrict__ jw)
{
    int idx = blockIdx.x * 256 + threadIdx.x;      // 18*128*64 = 147456
    if (idx >= 18*128*64) return;
    int cidx = idx >> 13;
    int rr   = idx & 8191;
    int oc   = rr >> 6;
    int k    = rr & 63;
    int tap  = cidx >> 1;
    int ic   = (cidx & 1)*64 + k;
    float v = jw[oc*(Cc*9) + ic*9 + tap];
    __nv_bfloat16 hi = __float2bfloat16(v);
    __nv_bfloat16 lo = __float2bfloat16(v - __bfloat162float(hi));
    g_whi[idx] = hi;
    g_wlo[idx] = lo;
}

// ---------------------------------------------------------------------------
// K3T: p = fused + coef  ->  NHWC bf16 hi/lo (transpose via smem)
// ---------------------------------------------------------------------------
__global__ __launch_bounds__(256) void k3t_transpose(const float* __restrict__ coef)
{
    const int px0 = blockIdx.x * 32;
    const int n   = blockIdx.y;
    const int tid = threadIdx.x;

    __shared__ __nv_bfloat16 s_hi[32][132];
    __shared__ __nv_bfloat16 s_lo[32][132];

    const int pxl = tid & 31;
#pragma unroll 4
    for (int pass = 0; pass < 16; pass++) {
        int c = pass*8 + (tid >> 5);
        size_t idx = ((size_t)(n*Cc + c))*HW + px0 + pxl;
        float v = g_fused[idx] + coef[idx];
        __nv_bfloat16 hi = __float2bfloat16(v);
        __nv_bfloat16 lo = __float2bfloat16(v - __bfloat162float(hi));
        s_hi[pxl][c] = hi;
        s_lo[pxl][c] = lo;
    }
    __syncthreads();

    const int pr = tid >> 3;
    const int j  = tid & 7;
    size_t dst = ((size_t)(n*HW) + px0 + pr)*Cc + j*16;
    uint32_t u[8];
#pragma unroll
    for (int k = 0; k < 8; k++) u[k] = *(const uint32_t*)&s_hi[pr][j*16 + k*2];
    ((uint4*)(g_phi + dst))[0] = make_uint4(u[0],u[1],u[2],u[3]);
    ((uint4*)(g_phi + dst))[1] = make_uint4(u[4],u[5],u[6],u[7]);
#pragma unroll
    for (int k = 0; k < 8; k++) u[k] = *(const uint32_t*)&s_lo[pr][j*16 + k*2];
    ((uint4*)(g_plo + dst))[0] = make_uint4(u[0],u[1],u[2],u[3]);
    ((uint4*)(g_plo + dst))[1] = make_uint4(u[4],u[5],u[6],u[7]);
}

// ---------------------------------------------------------------------------
// K4: joint 3x3 conv as implicit GEMM on warp MMA (bf16 3-term split),
// fused sigmoid-gating epilogue.
// Block tile: M=128 px x N=128 oc, K=1152 in 18 chunks of 64.
// 8 warps: warp_m = wid&3 (32 px), warp_n = wid>>2 (64 oc).
// smem tiles: rows of 64 bf16, stride 72 bf16 (144B) -> conflict-free frags.
// ---------------------------------------------------------------------------
#define SA_HI 0
#define SA_LO 18432
#define SW_HI 36864
#define SW_LO 55296
#define K4_SMEM 73728

__global__ __launch_bounds__(256) void k4_wmma(
    const float* __restrict__ coef,
    const float* __restrict__ jb,
    float* __restrict__ out)
{
    extern __shared__ char smem[];
    const int tid = threadIdx.x;
    const int wid = tid >> 5;
    const int lane = tid & 31;
    const int w0 = blockIdx.x * 128;
    const int h  = blockIdx.y;
    const int n  = blockIdx.z;

    const int r  = tid >> 1;         // tile row 0..127 (px for A, oc for W)
    const int hf = tid & 1;          // 64B half of the 128B row payload

    const int wm = (wid & 3) * 32;   // warp px offset
    const int wn = (wid >> 2) * 64;  // warp oc offset
    const int grp = lane >> 2;
    const int t4  = lane & 3;

    float d[2][8][4];
#pragma unroll
    for (int mf = 0; mf < 2; mf++)
#pragma unroll
        for (int nf = 0; nf < 8; nf++)
#pragma unroll
            for (int q = 0; q < 4; q++) d[mf][nf][q] = 0.f;

    const uint4 z4 = make_uint4(0,0,0,0);

    for (int cidx = 0; cidx < 18; cidx++) {
        const int tap = cidx >> 1;
        const int hk  = cidx & 1;
        const int dy = tap / 3, dx = tap % 3;
        const int hh = h + dy - 1;
        const int ww = w0 + dx - 1 + r;
        const bool val = (hh >= 0 && hh < Hh && ww >= 0 && ww < Ww);

        // gmem -> regs (start loads before the barrier)
        const size_t pix = (size_t)n*HW + (size_t)hh*Ww + ww;
        const uint4* pa_hi = (const uint4*)(g_phi + pix*Cc + hk*64 + hf*32);
        const uint4* pa_lo = (const uint4*)(g_plo + pix*Cc + hk*64 + hf*32);
        const uint4* pw_hi = (const uint4*)(g_whi + (size_t)cidx*8192 + r*64 + hf*32);
        const uint4* pw_lo = (const uint4*)(g_wlo + (size_t)cidx*8192 + r*64 + hf*32);
        uint4 vah[4], val4[4], vwh[4], vwl[4];
#pragma unroll
        for (int q = 0; q < 4; q++) {
            vah[q] = val ? pa_hi[q] : z4;
            val4[q] = val ? pa_lo[q] : z4;
            vwh[q] = pw_hi[q];
            vwl[q] = pw_lo[q];
        }

        __syncthreads();   // previous iteration's MMA reads done
        char* dst = smem + r*144 + hf*64;
#pragma unroll
        for (int q = 0; q < 4; q++) {
            *(uint4*)(dst + SA_HI + q*16) = vah[q];
            *(uint4*)(dst + SA_LO + q*16) = val4[q];
            *(uint4*)(dst + SW_HI + q*16) = vwh[q];
            *(uint4*)(dst + SW_LO + q*16) = vwl[q];
        }
        __syncthreads();

        // 4 k16 steps over this 64-wide chunk
#pragma unroll
        for (int s = 0; s < 4; s++) {
            const int kb = (s*16 + 2*t4) * 2;  // byte offset of this lane's k pair
            uint32_t ahi[2][4], alo[2][4];
#pragma unroll
            for (int mf = 0; mf < 2; mf++) {
                int row = wm + mf*16 + grp;
                const char* pa = smem + row*144 + kb;
                ahi[mf][0] = *(const uint32_t*)(pa + SA_HI);
                ahi[mf][1] = *(const uint32_t*)(pa + SA_HI + 8*144);
                ahi[mf][2] = *(const uint32_t*)(pa + SA_HI + 16);
                ahi[mf][3] = *(const uint32_t*)(pa + SA_HI + 8*144 + 16);
                alo[mf][0] = *(const uint32_t*)(pa + SA_LO);
                alo[mf][1] = *(const uint32_t*)(pa + SA_LO + 8*144);
                alo[mf][2] = *(const uint32_t*)(pa + SA_LO + 16);
                alo[mf][3] = *(const uint32_t*)(pa + SA_LO + 8*144 + 16);
            }
#pragma unroll
            for (int nf = 0; nf < 8; nf++) {
                int nr = wn + nf*8 + grp;
                const char* pw = smem + nr*144 + kb;
                uint32_t bh0 = *(const uint32_t*)(pw + SW_HI);
                uint32_t bh1 = *(const uint32_t*)(pw + SW_HI + 16);
                uint32_t bl0 = *(const uint32_t*)(pw + SW_LO);
                uint32_t bl1 = *(const uint32_t*)(pw + SW_LO + 16);
#pragma unroll
                for (int mf = 0; mf < 2; mf++) {
                    mma16816(d[mf][nf], ahi[mf], bh0, bh1);
                    mma16816(d[mf][nf], ahi[mf], bl0, bl1);
                    mma16816(d[mf][nf], alo[mf], bh0, bh1);
                }
            }
        }
    }

    // stage D to smem as [oc][px] for a coalesced epilogue
    __syncthreads();
    float* sD = (float*)smem;            // 128 x 132 floats (67.6 KB)
#pragma unroll
    for (int mf = 0; mf < 2; mf++) {
#pragma unroll
        for (int nf = 0; nf < 8; nf++) {
            int row = wm + mf*16 + grp;
            int col = wn + nf*8 + 2*t4;
            sD[(col  )*132 + row    ] = d[mf][nf][0];
            sD[(col+1)*132 + row    ] = d[mf][nf][1];
            sD[(col  )*132 + row + 8] = d[mf][nf][2];
            sD[(col+1)*132 + row + 8] = d[mf][nf][3];
        }
    }
    __syncthreads();

    const size_t nplane = (size_t)n*Cc*HW;
    const int px = (tid & 31) * 4;
#pragma unroll 2
    for (int j = 0; j < 16; j++) {
        int oc = (tid >> 5) + j*8;
        float4 a4 = *(const float4*)&sD[oc*132 + px];
        float b = jb[oc];
        size_t base = nplane + (size_t)oc*HW + (size_t)h*Ww + w0 + px;
        float4 fu = *(const float4*)&g_fused[base];
        float4 cf = *(const float4*)&coef[base];
        float4 o;
        {
            float p2 = 1.f/(1.f + __expf(-(a4.x + b))); o.x = fu.x + p2*(cf.x - fu.x);
        }
        {
            float p2 = 1.f/(1.f + __expf(-(a4.y + b))); o.y = fu.y + p2*(cf.y - fu.y);
        }
        {
            float p2 = 1.f/(1.f + __expf(-(a4.z + b))); o.z = fu.z + p2*(cf.z - fu.z);
        }
        {
            float p2 = 1.f/(1.f + __expf(-(a4.w + b))); o.w = fu.w + p2*(cf.w - fu.w);
        }
        *(float4*)(out + base) = o;
    }
}

// ---------------------------------------------------------------------------
extern "C" void kernel_launch(void* const* d_in, const int* in_sizes, int n_in,
                              void* d_out, int out_size)
{
    const float* coef  = (const float*)d_in[0];
    const float* ms    = (const float*)d_in[1];
    const float* fix_w = (const float*)d_in[2];
    const float* bn1_g = (const float*)d_in[3];
    const float* bn1_b = (const float*)d_in[4];
    const float* bn1_m = (const float*)d_in[5];
    const float* bn1_v = (const float*)d_in[6];
    const float* dyn_w = (const float*)d_in[7];
    const float* dyn_b = (const float*)d_in[8];
    const float* bn2_g = (const float*)d_in[9];
    const float* bn2_b = (const float*)d_in[10];
    const float* bn2_m = (const float*)d_in[11];
    const float* bn2_v = (const float*)d_in[12];
    const float* refine_w = (const float*)d_in[13];
    const float* refine_b = (const float*)d_in[14];
    const float* joint_w  = (const float*)d_in[15];
    const float* joint_b  = (const float*)d_in[16];
    float* outp = (float*)d_out;

    cudaFuncSetAttribute(k4_wmma, cudaFuncAttributeMaxDynamicSharedMemorySize, K4_SMEM);

    kw_prep<<<(18*128*64 + 255)/256, 256>>>(joint_w);
    k1_dynkernel<<<dim3(Ww/128, Hh, Nn), 128>>>(ms, dyn_w, dyn_b);
    k2_cat<<<dim3(Hh, Cc, Nn), 256>>>(ms, fix_w,
                                      bn1_g, bn1_b, bn1_m, bn1_v,
                                      bn2_g, bn2_b, bn2_m, bn2_v);
    k3_refine<<<dim3(HW/64, 1, Nn), 256>>>(refine_w, refine_b);
    k3t_transpose<<<dim3(HW/32, Nn), 256>>>(coef);
    k4_wmma<<<dim3(Ww/128, Hh, Nn), 256, K4_SMEM>>>(coef, joint_b, outp);
}

// round 4
// speedup vs baseline: 1.8036x; 1.1556x over previous
#include <cuda_runtime.h>
#include <cuda_bf16.h>
#include <cstdint>

#define Nn 4
#define Cc 128
#define Hh 256
#define Ww 256
#define HW (Hh*Ww)

// ---------------- scratch (device globals; allocation-free) ----------------
__device__ float g_dk[(size_t)Nn*9*HW];                            // dyn kernels
__device__ float g_fused[(size_t)Nn*Cc*HW];                        // refine out NCHW
__device__ __align__(256) __nv_bfloat16 g_chi[(size_t)Nn*HW*256];  // cat NHWC hi
__device__ __align__(256) __nv_bfloat16 g_clo[(size_t)Nn*HW*256];  // cat NHWC lo
__device__ __align__(256) __nv_bfloat16 g_phi[(size_t)Nn*HW*Cc];   // p NHWC hi
__device__ __align__(256) __nv_bfloat16 g_plo[(size_t)Nn*HW*Cc];   // p NHWC lo
__device__ __align__(256) __nv_bfloat16 g_whi[18*128*64];          // joint W hi
__device__ __align__(256) __nv_bfloat16 g_wlo[18*128*64];          // joint W lo
__device__ __align__(256) __nv_bfloat16 g_rwhi[4*128*64];          // refine W hi
__device__ __align__(256) __nv_bfloat16 g_rwlo[4*128*64];          // refine W lo

// ---------------------------------------------------------------------------
__device__ __forceinline__ void mma16816(float* d, const uint32_t* a,
                                         uint32_t b0, uint32_t b1) {
    asm volatile(
        "mma.sync.aligned.m16n8k16.row.col.f32.bf16.bf16.f32 "
        "{%0,%1,%2,%3}, {%4,%5,%6,%7}, {%8,%9}, {%0,%1,%2,%3};"
        : "+f"(d[0]), "+f"(d[1]), "+f"(d[2]), "+f"(d[3])
        : "r"(a[0]), "r"(a[1]), "r"(a[2]), "r"(a[3]), "r"(b0), "r"(b1));
}
__device__ __forceinline__ uint32_t pack_bf2(__nv_bfloat16 a, __nv_bfloat16 b) {
    __nv_bfloat162 h2; h2.x = a; h2.y = b;
    return *(uint32_t*)&h2;
}

// ---------------------------------------------------------------------------
// K1: dyn_kernel conv(ms, dyn_w[9,128,3,3]) + b, L1-normalized over 9 taps
// ---------------------------------------------------------------------------
__global__ __launch_bounds__(128) void k1_dynkernel(
    const float* __restrict__ ms,
    const float* __restrict__ dyn_w,
    const float* __restrict__ dyn_b)
{
    const int w0 = blockIdx.x * 128;
    const int h  = blockIdx.y;
    const int n  = blockIdx.z;
    const int tid = threadIdx.x;

    __shared__ float Xs[3][130];
    __shared__ float Wsm[9][9];

    float acc[9];
#pragma unroll
    for (int k = 0; k < 9; k++) acc[k] = dyn_b[k];

    for (int ic = 0; ic < Cc; ic++) {
        const float* mp = ms + ((size_t)(n*Cc + ic))*HW;
        for (int idx = tid; idx < 3*130; idx += 128) {
            int r = idx / 130, cc2 = idx % 130;
            int hh = h + r - 1, ww = w0 + cc2 - 1;
            float v = 0.f;
            if (hh >= 0 && hh < Hh && ww >= 0 && ww < Ww) v = mp[hh*Ww + ww];
            Xs[r][cc2] = v;
        }
        if (tid < 81)
            Wsm[tid/9][tid%9] = dyn_w[(tid/9)*(Cc*9) + ic*9 + (tid%9)];
        __syncthreads();

#pragma unroll
        for (int tap = 0; tap < 9; tap++) {
            float xv = Xs[tap/3][tid + (tap%3)];
#pragma unroll
            for (int k = 0; k < 9; k++) acc[k] += Wsm[k][tap] * xv;
        }
        __syncthreads();
    }

    float denom = 0.f;
#pragma unroll
    for (int k = 0; k < 9; k++) denom += fabsf(acc[k]);
    float inv = 1.f / denom;
#pragma unroll
    for (int k = 0; k < 9; k++)
        g_dk[((size_t)(n*9 + k))*HW + (size_t)h*Ww + w0 + tid] = acc[k] * inv;
}

// ---------------------------------------------------------------------------
// K2: concat tensor directly in NHWC bf16 hi/lo.
// Block: 32 px of one row; 256 thr = 8 ch x 32 px; 16 channel groups.
// cat channel c in [0,128): dyn, [128,256): fix.
// ---------------------------------------------------------------------------
__global__ __launch_bounds__(256) void k2_cat_nhwc(
    const float* __restrict__ ms,
    const float* __restrict__ fix_w,
    const float* __restrict__ bn1_g, const float* __restrict__ bn1_b,
    const float* __restrict__ bn1_m, const float* __restrict__ bn1_v,
    const float* __restrict__ bn2_g, const float* __restrict__ bn2_b,
    const float* __restrict__ bn2_m, const float* __restrict__ bn2_v)
{
    const int w0 = blockIdx.x * 32;
    const int h  = blockIdx.y;
    const int n  = blockIdx.z;
    const int tid = threadIdx.x;

    __shared__ float dks[9][32];
    __shared__ float Xs[8][3][34];
    __shared__ __nv_bfloat16 s_hi[32][264];
    __shared__ __nv_bfloat16 s_lo[32][264];

    for (int idx = tid; idx < 288; idx += 256) {
        int tap = idx >> 5, px = idx & 31;
        dks[tap][px] = g_dk[((size_t)(n*9 + tap))*HW + (size_t)h*Ww + w0 + px];
    }

    const int ci = tid >> 5;
    const int px = tid & 31;

    for (int cg = 0; cg < 16; cg++) {
        __syncthreads();
        for (int idx = tid; idx < 816; idx += 256) {
            int cc2 = idx / 102; int rem = idx % 102;
            int r = rem / 34; int col = rem % 34;
            int hh = h + r - 1, ww = w0 + col - 1;
            float v = 0.f;
            if (hh >= 0 && hh < Hh && ww >= 0 && ww < Ww)
                v = ms[((size_t)(n*Cc + cg*8 + cc2))*HW + (size_t)hh*Ww + ww];
            Xs[cc2][r][col] = v;
        }
        __syncthreads();

        const int c = cg*8 + ci;
        float fwv[9];
#pragma unroll
        for (int tap = 0; tap < 9; tap++) fwv[tap] = fix_w[c*9 + tap];

        float f = 0.f, d = 0.f;
#pragma unroll
        for (int tap = 0; tap < 9; tap++) {
            float xv = Xs[ci][tap/3][px + (tap%3)];
            f += fwv[tap] * xv;
            d += dks[tap][px] * xv;
        }
        float s1 = bn1_g[c] * rsqrtf(bn1_v[c] + 1e-5f);
        float t1 = bn1_b[c] - bn1_m[c]*s1;
        float s2 = bn2_g[c] * rsqrtf(bn2_v[c] + 1e-5f);
        float t2 = bn2_b[c] - bn2_m[c]*s2;
        float dynv = fmaxf(d*s2 + t2, 0.f);
        float fixv = fmaxf(f*s1 + t1, 0.f);

        __nv_bfloat16 dh = __float2bfloat16(dynv);
        __nv_bfloat16 dl = __float2bfloat16(dynv - __bfloat162float(dh));
        __nv_bfloat16 fh = __float2bfloat16(fixv);
        __nv_bfloat16 fl = __float2bfloat16(fixv - __bfloat162float(fh));
        s_hi[px][c]       = dh;  s_lo[px][c]       = dl;
        s_hi[px][128 + c] = fh;  s_lo[px][128 + c] = fl;
    }
    __syncthreads();

    const int opx = tid >> 3;
    const int sub = tid & 7;
    size_t base = ((size_t)(n*HW) + (size_t)h*Ww + w0 + opx)*256 + sub*32;
    const uint4* sh = (const uint4*)&s_hi[opx][sub*32];
    const uint4* sl = (const uint4*)&s_lo[opx][sub*32];
#pragma unroll
    for (int q = 0; q < 4; q++) ((uint4*)(g_chi + base))[q] = sh[q];
#pragma unroll
    for (int q = 0; q < 4; q++) ((uint4*)(g_clo + base))[q] = sl[q];
}

// ---------------------------------------------------------------------------
// Weight prep: hi/lo bf16 split into K-chunked layouts
// ---------------------------------------------------------------------------
__global__ __launch_bounds__(256) void kw_prep(const float* __restrict__ jw)
{
    int idx = blockIdx.x * 256 + threadIdx.x;      // 18*128*64
    if (idx >= 18*128*64) return;
    int cidx = idx >> 13;
    int rr   = idx & 8191;
    int oc   = rr >> 6;
    int k    = rr & 63;
    int tap  = cidx >> 1;
    int ic   = (cidx & 1)*64 + k;
    float v = jw[oc*(Cc*9) + ic*9 + tap];
    __nv_bfloat16 hi = __float2bfloat16(v);
    __nv_bfloat16 lo = __float2bfloat16(v - __bfloat162float(hi));
    g_whi[idx] = hi;
    g_wlo[idx] = lo;
}

__global__ __launch_bounds__(256) void krw_prep(const float* __restrict__ rw)
{
    int idx = blockIdx.x * 256 + threadIdx.x;      // 4*128*64
    if (idx >= 4*128*64) return;
    int ck = idx >> 13;
    int rr = idx & 8191;
    int oc = rr >> 6;
    int k  = rr & 63;
    float v = rw[oc*256 + ck*64 + k];
    __nv_bfloat16 hi = __float2bfloat16(v);
    __nv_bfloat16 lo = __float2bfloat16(v - __bfloat162float(hi));
    g_rwhi[idx] = hi;
    g_rwlo[idx] = lo;
}

// ---------------------------------------------------------------------------
// shared GEMM smem layout (bf16 rows of 64, stride 144B)
// ---------------------------------------------------------------------------
#define SA_HI 0
#define SA_LO 18432
#define SW_HI 36864
#define SW_LO 55296
#define GEMM_SMEM 73728

// ---------------------------------------------------------------------------
// K3: refine 1x1 as HMMA GEMM (K=256, 4 chunks). Epilogue writes
// g_fused (NCHW fp32) and p = fused+coef -> g_phi/g_plo (NHWC bf16 hi/lo).
// ---------------------------------------------------------------------------
__global__ __launch_bounds__(256) void k3_mma(
    const float* __restrict__ coef,
    const float* __restrict__ rb,
    int dummy)
{
    extern __shared__ char smem[];
    __shared__ float s_rb[128];
    const int tid = threadIdx.x;
    const int wid = tid >> 5;
    const int lane = tid & 31;
    const int p0 = blockIdx.x * 128;
    const int n  = blockIdx.z;

    if (tid < 128) s_rb[tid] = rb[tid];

    const int r  = tid >> 1;
    const int hf = tid & 1;
    const int wm = (wid & 3) * 32;
    const int wn = (wid >> 2) * 64;
    const int grp = lane >> 2;
    const int t4  = lane & 3;

    float d[2][8][4];
#pragma unroll
    for (int mf = 0; mf < 2; mf++)
#pragma unroll
        for (int nf = 0; nf < 8; nf++)
#pragma unroll
            for (int q = 0; q < 4; q++) d[mf][nf][q] = 0.f;

    for (int ck = 0; ck < 4; ck++) {
        const uint4* pa_hi = (const uint4*)(g_chi + ((size_t)(n*HW) + p0 + r)*256 + ck*64 + hf*32);
        const uint4* pa_lo = (const uint4*)(g_clo + ((size_t)(n*HW) + p0 + r)*256 + ck*64 + hf*32);
        const uint4* pw_hi = (const uint4*)(g_rwhi + (size_t)ck*8192 + r*64 + hf*32);
        const uint4* pw_lo = (const uint4*)(g_rwlo + (size_t)ck*8192 + r*64 + hf*32);
        uint4 vah[4], val4[4], vwh[4], vwl[4];
#pragma unroll
        for (int q = 0; q < 4; q++) {
            vah[q] = pa_hi[q]; val4[q] = pa_lo[q];
            vwh[q] = pw_hi[q]; vwl[q] = pw_lo[q];
        }
        __syncthreads();
        char* dst = smem + r*144 + hf*64;
#pragma unroll
        for (int q = 0; q < 4; q++) {
            *(uint4*)(dst + SA_HI + q*16) = vah[q];
            *(uint4*)(dst + SA_LO + q*16) = val4[q];
            *(uint4*)(dst + SW_HI + q*16) = vwh[q];
            *(uint4*)(dst + SW_LO + q*16) = vwl[q];
        }
        __syncthreads();

#pragma unroll
        for (int s = 0; s < 4; s++) {
            const int kb = (s*16 + 2*t4) * 2;
            uint32_t ahi[2][4], alo[2][4];
#pragma unroll
            for (int mf = 0; mf < 2; mf++) {
                int row = wm + mf*16 + grp;
                const char* pa = smem + row*144 + kb;
                ahi[mf][0] = *(const uint32_t*)(pa + SA_HI);
                ahi[mf][1] = *(const uint32_t*)(pa + SA_HI + 8*144);
                ahi[mf][2] = *(const uint32_t*)(pa + SA_HI + 16);
                ahi[mf][3] = *(const uint32_t*)(pa + SA_HI + 8*144 + 16);
                alo[mf][0] = *(const uint32_t*)(pa + SA_LO);
                alo[mf][1] = *(const uint32_t*)(pa + SA_LO + 8*144);
                alo[mf][2] = *(const uint32_t*)(pa + SA_LO + 16);
                alo[mf][3] = *(const uint32_t*)(pa + SA_LO + 8*144 + 16);
            }
#pragma unroll
            for (int nf = 0; nf < 8; nf++) {
                int nr = wn + nf*8 + grp;
                const char* pw = smem + nr*144 + kb;
                uint32_t bh0 = *(const uint32_t*)(pw + SW_HI);
                uint32_t bh1 = *(const uint32_t*)(pw + SW_HI + 16);
                uint32_t bl0 = *(const uint32_t*)(pw + SW_LO);
                uint32_t bl1 = *(const uint32_t*)(pw + SW_LO + 16);
#pragma unroll
                for (int mf = 0; mf < 2; mf++) {
                    mma16816(d[mf][nf], ahi[mf], bh0, bh1);
                    mma16816(d[mf][nf], ahi[mf], bl0, bl1);
                    mma16816(d[mf][nf], alo[mf], bh0, bh1);
                }
            }
        }
    }

    __syncthreads();
    float* sD = (float*)smem;    // [128 oc][132 px]
#pragma unroll
    for (int mf = 0; mf < 2; mf++)
#pragma unroll
        for (int nf = 0; nf < 8; nf++) {
            int row = wm + mf*16 + grp;
            int col = wn + nf*8 + 2*t4;
            sD[(col  )*132 + row    ] = d[mf][nf][0];
            sD[(col+1)*132 + row    ] = d[mf][nf][1];
            sD[(col  )*132 + row + 8] = d[mf][nf][2];
            sD[(col+1)*132 + row + 8] = d[mf][nf][3];
        }
    __syncthreads();

    const size_t nplane = (size_t)n*Cc*HW;

    // pass 1: fused (NCHW fp32, coalesced)
    {
        const int pxq = (tid & 31) * 4;
#pragma unroll 2
        for (int j = 0; j < 16; j++) {
            int oc = (tid >> 5) + j*8;
            float4 a4 = *(const float4*)&sD[oc*132 + pxq];
            float b = s_rb[oc];
            float4 o = make_float4(a4.x + b, a4.y + b, a4.z + b, a4.w + b);
            *(float4*)(g_fused + nplane + (size_t)oc*HW + p0 + pxq) = o;
        }
    }

    // pass 2: p = fused + coef -> NHWC bf16 hi/lo
    {
        const int px2 = tid >> 1;
        const int half = tid & 1;
        uint32_t hp[16], lp[16];
#pragma unroll
        for (int jj = 0; jj < 16; jj++) {
            uint32_t h01 = 0, l01 = 0;
            __nv_bfloat16 hv[4], lv[4];
#pragma unroll
            for (int e = 0; e < 4; e++) {
                int oc = half*64 + jj*4 + e;
                float v = sD[oc*132 + px2] + s_rb[oc]
                        + coef[nplane + (size_t)oc*HW + p0 + px2];
                hv[e] = __float2bfloat16(v);
                lv[e] = __float2bfloat16(v - __bfloat162float(hv[e]));
            }
            hp[jj] = pack_bf2(hv[0], hv[1]);
            lp[jj] = pack_bf2(lv[0], lv[1]);
            h01 = pack_bf2(hv[2], hv[3]);
            l01 = pack_bf2(lv[2], lv[3]);
            // store pairs immediately as 64-bit to cut register pressure
            size_t dst = ((size_t)(n*HW) + p0 + px2)*128 + half*64 + jj*4;
            *(uint2*)(g_phi + dst) = make_uint2(hp[jj], h01);
            *(uint2*)(g_plo + dst) = make_uint2(lp[jj], l01);
        }
    }
}

// ---------------------------------------------------------------------------
// K4: joint 3x3 conv as HMMA implicit GEMM + sigmoid-gating epilogue.
// ---------------------------------------------------------------------------
__global__ __launch_bounds__(256) void k4_wmma(
    const float* __restrict__ coef,
    const float* __restrict__ jb,
    float* __restrict__ out)
{
    extern __shared__ char smem[];
    const int tid = threadIdx.x;
    const int wid = tid >> 5;
    const int lane = tid & 31;
    const int w0 = blockIdx.x * 128;
    const int h  = blockIdx.y;
    const int n  = blockIdx.z;

    const int r  = tid >> 1;
    const int hf = tid & 1;
    const int wm = (wid & 3) * 32;
    const int wn = (wid >> 2) * 64;
    const int grp = lane >> 2;
    const int t4  = lane & 3;

    float d[2][8][4];
#pragma unroll
    for (int mf = 0; mf < 2; mf++)
#pragma unroll
        for (int nf = 0; nf < 8; nf++)
#pragma unroll
            for (int q = 0; q < 4; q++) d[mf][nf][q] = 0.f;

    const uint4 z4 = make_uint4(0,0,0,0);

    for (int cidx = 0; cidx < 18; cidx++) {
        const int tap = cidx >> 1;
        const int hk  = cidx & 1;
        const int dy = tap / 3, dx = tap % 3;
        const int hh = h + dy - 1;
        const int ww = w0 + dx - 1 + r;
        const bool val = (hh >= 0 && hh < Hh && ww >= 0 && ww < Ww);

        const size_t pix = (size_t)n*HW + (size_t)hh*Ww + ww;
        const uint4* pa_hi = (const uint4*)(g_phi + pix*Cc + hk*64 + hf*32);
        const uint4* pa_lo = (const uint4*)(g_plo + pix*Cc + hk*64 + hf*32);
        const uint4* pw_hi = (const uint4*)(g_whi + (size_t)cidx*8192 + r*64 + hf*32);
        const uint4* pw_lo = (const uint4*)(g_wlo + (size_t)cidx*8192 + r*64 + hf*32);
        uint4 vah[4], val4[4], vwh[4], vwl[4];
#pragma unroll
        for (int q = 0; q < 4; q++) {
            vah[q] = val ? pa_hi[q] : z4;
            val4[q] = val ? pa_lo[q] : z4;
            vwh[q] = pw_hi[q];
            vwl[q] = pw_lo[q];
        }

        __syncthreads();
        char* dst = smem + r*144 + hf*64;
#pragma unroll
        for (int q = 0; q < 4; q++) {
            *(uint4*)(dst + SA_HI + q*16) = vah[q];
            *(uint4*)(dst + SA_LO + q*16) = val4[q];
            *(uint4*)(dst + SW_HI + q*16) = vwh[q];
            *(uint4*)(dst + SW_LO + q*16) = vwl[q];
        }
        __syncthreads();

#pragma unroll
        for (int s = 0; s < 4; s++) {
            const int kb = (s*16 + 2*t4) * 2;
            uint32_t ahi[2][4], alo[2][4];
#pragma unroll
            for (int mf = 0; mf < 2; mf++) {
                int row = wm + mf*16 + grp;
                const char* pa = smem + row*144 + kb;
                ahi[mf][0] = *(const uint32_t*)(pa + SA_HI);
                ahi[mf][1] = *(const uint32_t*)(pa + SA_HI + 8*144);
                ahi[mf][2] = *(const uint32_t*)(pa + SA_HI + 16);
                ahi[mf][3] = *(const uint32_t*)(pa + SA_HI + 8*144 + 16);
                alo[mf][0] = *(const uint32_t*)(pa + SA_LO);
                alo[mf][1] = *(const uint32_t*)(pa + SA_LO + 8*144);
                alo[mf][2] = *(const uint32_t*)(pa + SA_LO + 16);
                alo[mf][3] = *(const uint32_t*)(pa + SA_LO + 8*144 + 16);
            }
#pragma unroll
            for (int nf = 0; nf < 8; nf++) {
                int nr = wn + nf*8 + grp;
                const char* pw = smem + nr*144 + kb;
                uint32_t bh0 = *(const uint32_t*)(pw + SW_HI);
                uint32_t bh1 = *(const uint32_t*)(pw + SW_HI + 16);
                uint32_t bl0 = *(const uint32_t*)(pw + SW_LO);
                uint32_t bl1 = *(const uint32_t*)(pw + SW_LO + 16);
#pragma unroll
                for (int mf = 0; mf < 2; mf++) {
                    mma16816(d[mf][nf], ahi[mf], bh0, bh1);
                    mma16816(d[mf][nf], ahi[mf], bl0, bl1);
                    mma16816(d[mf][nf], alo[mf], bh0, bh1);
                }
            }
        }
    }

    __syncthreads();
    float* sD = (float*)smem;
#pragma unroll
    for (int mf = 0; mf < 2; mf++)
#pragma unroll
        for (int nf = 0; nf < 8; nf++) {
            int row = wm + mf*16 + grp;
            int col = wn + nf*8 + 2*t4;
            sD[(col  )*132 + row    ] = d[mf][nf][0];
            sD[(col+1)*132 + row    ] = d[mf][nf][1];
            sD[(col  )*132 + row + 8] = d[mf][nf][2];
            sD[(col+1)*132 + row + 8] = d[mf][nf][3];
        }
    __syncthreads();

    const size_t nplane = (size_t)n*Cc*HW;
    const int px = (tid & 31) * 4;
#pragma unroll 2
    for (int j = 0; j < 16; j++) {
        int oc = (tid >> 5) + j*8;
        float4 a4 = *(const float4*)&sD[oc*132 + px];
        float b = jb[oc];
        size_t base = nplane + (size_t)oc*HW + (size_t)h*Ww + w0 + px;
        float4 fu = *(const float4*)&g_fused[base];
        float4 cf = *(const float4*)&coef[base];
        float4 o;
        { float p2 = 1.f/(1.f + __expf(-(a4.x + b))); o.x = fu.x + p2*(cf.x - fu.x); }
        { float p2 = 1.f/(1.f + __expf(-(a4.y + b))); o.y = fu.y + p2*(cf.y - fu.y); }
        { float p2 = 1.f/(1.f + __expf(-(a4.z + b))); o.z = fu.z + p2*(cf.z - fu.z); }
        { float p2 = 1.f/(1.f + __expf(-(a4.w + b))); o.w = fu.w + p2*(cf.w - fu.w); }
        *(float4*)(out + base) = o;
    }
}

// ---------------------------------------------------------------------------
extern "C" void kernel_launch(void* const* d_in, const int* in_sizes, int n_in,
                              void* d_out, int out_size)
{
    const float* coef  = (const float*)d_in[0];
    const float* ms    = (const float*)d_in[1];
    const float* fix_w = (const float*)d_in[2];
    const float* bn1_g = (const float*)d_in[3];
    const float* bn1_b = (const float*)d_in[4];
    const float* bn1_m = (const float*)d_in[5];
    const float* bn1_v = (const float*)d_in[6];
    const float* dyn_w = (const float*)d_in[7];
    const float* dyn_b = (const float*)d_in[8];
    const float* bn2_g = (const float*)d_in[9];
    const float* bn2_b = (const float*)d_in[10];
    const float* bn2_m = (const float*)d_in[11];
    const float* bn2_v = (const float*)d_in[12];
    const float* refine_w = (const float*)d_in[13];
    const float* refine_b = (const float*)d_in[14];
    const float* joint_w  = (const float*)d_in[15];
    const float* joint_b  = (const float*)d_in[16];
    float* outp = (float*)d_out;

    cudaFuncSetAttribute(k3_mma,  cudaFuncAttributeMaxDynamicSharedMemorySize, GEMM_SMEM);
    cudaFuncSetAttribute(k4_wmma, cudaFuncAttributeMaxDynamicSharedMemorySize, GEMM_SMEM);

    kw_prep<<<(18*128*64 + 255)/256, 256>>>(joint_w);
    krw_prep<<<(4*128*64 + 255)/256, 256>>>(refine_w);
    k1_dynkernel<<<dim3(Ww/128, Hh, Nn), 128>>>(ms, dyn_w, dyn_b);
    k2_cat_nhwc<<<dim3(Ww/32, Hh, Nn), 256>>>(ms, fix_w,
                                              bn1_g, bn1_b, bn1_m, bn1_v,
                                              bn2_g, bn2_b, bn2_m, bn2_v);
    k3_mma<<<dim3(HW/128, 1, Nn), 256, GEMM_SMEM>>>(coef, refine_b, 0);
    k4_wmma<<<dim3(Ww/128, Hh, Nn), 256, GEMM_SMEM>>>(coef, joint_b, outp);
}

// round 5
// speedup vs baseline: 1.8167x; 1.0072x over previous
#include <cuda_runtime.h>
#include <cuda_bf16.h>
#include <cstdint>

#define Nn 4
#define Cc 128
#define Hh 256
#define Ww 256
#define HW (Hh*Ww)

// ---------------- scratch (device globals; allocation-free) ----------------
__device__ float g_dk[(size_t)Nn*9*HW];                            // dyn kernels
__device__ float g_fused[(size_t)Nn*Cc*HW];                        // refine out NCHW
__device__ __align__(256) __nv_bfloat16 g_chi[(size_t)Nn*HW*256];  // cat NHWC hi
__device__ __align__(256) __nv_bfloat16 g_clo[(size_t)Nn*HW*256];  // cat NHWC lo
__device__ __align__(256) __nv_bfloat16 g_phi[(size_t)Nn*HW*Cc];   // p NHWC hi
__device__ __align__(256) __nv_bfloat16 g_plo[(size_t)Nn*HW*Cc];   // p NHWC lo
__device__ __align__(256) __nv_bfloat16 g_whi[18*128*64];          // joint W hi
__device__ __align__(256) __nv_bfloat16 g_wlo[18*128*64];          // joint W lo
__device__ __align__(256) __nv_bfloat16 g_rwhi[4*128*64];          // refine W hi
__device__ __align__(256) __nv_bfloat16 g_rwlo[4*128*64];          // refine W lo

// ---------------------------------------------------------------------------
__device__ __forceinline__ void mma16816(float* d, const uint32_t* a,
                                         uint32_t b0, uint32_t b1) {
    asm volatile(
        "mma.sync.aligned.m16n8k16.row.col.f32.bf16.bf16.f32 "
        "{%0,%1,%2,%3}, {%4,%5,%6,%7}, {%8,%9}, {%0,%1,%2,%3};"
        : "+f"(d[0]), "+f"(d[1]), "+f"(d[2]), "+f"(d[3])
        : "r"(a[0]), "r"(a[1]), "r"(a[2]), "r"(a[3]), "r"(b0), "r"(b1));
}
__device__ __forceinline__ void ldmat_x4(uint32_t* r, uint32_t saddr) {
    asm volatile("ldmatrix.sync.aligned.m8n8.x4.shared.b16 {%0,%1,%2,%3}, [%4];"
        : "=r"(r[0]), "=r"(r[1]), "=r"(r[2]), "=r"(r[3]) : "r"(saddr));
}
__device__ __forceinline__ uint32_t pack_bf2(__nv_bfloat16 a, __nv_bfloat16 b) {
    __nv_bfloat162 h2; h2.x = a; h2.y = b;
    return *(uint32_t*)&h2;
}

// ---------------------------------------------------------------------------
// K1: dyn_kernel conv(ms, dyn_w[9,128,3,3]) + b, L1-normalized over 9 taps
// ---------------------------------------------------------------------------
__global__ __launch_bounds__(128) void k1_dynkernel(
    const float* __restrict__ ms,
    const float* __restrict__ dyn_w,
    const float* __restrict__ dyn_b)
{
    const int w0 = blockIdx.x * 128;
    const int h  = blockIdx.y;
    const int n  = blockIdx.z;
    const int tid = threadIdx.x;

    __shared__ float Xs[3][130];
    __shared__ float Wsm[9][9];

    float acc[9];
#pragma unroll
    for (int k = 0; k < 9; k++) acc[k] = dyn_b[k];

    for (int ic = 0; ic < Cc; ic++) {
        const float* mp = ms + ((size_t)(n*Cc + ic))*HW;
        for (int idx = tid; idx < 3*130; idx += 128) {
            int r = idx / 130, cc2 = idx % 130;
            int hh = h + r - 1, ww = w0 + cc2 - 1;
            float v = 0.f;
            if (hh >= 0 && hh < Hh && ww >= 0 && ww < Ww) v = mp[hh*Ww + ww];
            Xs[r][cc2] = v;
        }
        if (tid < 81)
            Wsm[tid/9][tid%9] = dyn_w[(tid/9)*(Cc*9) + ic*9 + (tid%9)];
        __syncthreads();

#pragma unroll
        for (int tap = 0; tap < 9; tap++) {
            float xv = Xs[tap/3][tid + (tap%3)];
#pragma unroll
            for (int k = 0; k < 9; k++) acc[k] += Wsm[k][tap] * xv;
        }
        __syncthreads();
    }

    float denom = 0.f;
#pragma unroll
    for (int k = 0; k < 9; k++) denom += fabsf(acc[k]);
    float inv = 1.f / denom;
#pragma unroll
    for (int k = 0; k < 9; k++)
        g_dk[((size_t)(n*9 + k))*HW + (size_t)h*Ww + w0 + tid] = acc[k] * inv;
}

// ---------------------------------------------------------------------------
// K2: concat tensor in NHWC bf16 hi/lo. Hoisted BN/fix_w, warp-per-ch loads.
// ---------------------------------------------------------------------------
__global__ __launch_bounds__(256) void k2_cat_nhwc(
    const float* __restrict__ ms,
    const float* __restrict__ fix_w,
    const float* __restrict__ bn1_g, const float* __restrict__ bn1_b,
    const float* __restrict__ bn1_m, const float* __restrict__ bn1_v,
    const float* __restrict__ bn2_g, const float* __restrict__ bn2_b,
    const float* __restrict__ bn2_m, const float* __restrict__ bn2_v)
{
    const int w0 = blockIdx.x * 32;
    const int h  = blockIdx.y;
    const int n  = blockIdx.z;
    const int tid = threadIdx.x;
    const int lane = tid & 31;

    __shared__ float dks[9][32];
    __shared__ float Xs[8][3][34];
    __shared__ float s1a[128], t1a[128], s2a[128], t2a[128];
    __shared__ float fws[128][10];
    __shared__ __nv_bfloat16 s_hi[32][264];
    __shared__ __nv_bfloat16 s_lo[32][264];

    if (tid < 128) {
        float s1 = bn1_g[tid] * rsqrtf(bn1_v[tid] + 1e-5f);
        s1a[tid] = s1; t1a[tid] = bn1_b[tid] - bn1_m[tid]*s1;
        float s2 = bn2_g[tid] * rsqrtf(bn2_v[tid] + 1e-5f);
        s2a[tid] = s2; t2a[tid] = bn2_b[tid] - bn2_m[tid]*s2;
    }
    for (int idx = tid; idx < 1152; idx += 256)
        fws[idx/9][idx%9] = fix_w[idx];
    for (int idx = tid; idx < 288; idx += 256) {
        int tap = idx >> 5, px = idx & 31;
        dks[tap][px] = g_dk[((size_t)(n*9 + tap))*HW + (size_t)h*Ww + w0 + px];
    }

    const int ci = tid >> 5;
    const int px = lane;

    for (int cg = 0; cg < 16; cg++) {
        __syncthreads();
        {
            const int ch = cg*8 + ci;
            const float* mp = ms + ((size_t)(n*Cc + ch))*HW;
#pragma unroll
            for (int r = 0; r < 3; r++) {
                int hh = h + r - 1;
                bool rok = (hh >= 0 && hh < Hh);
#pragma unroll
                for (int j0 = 0; j0 < 2; j0++) {
                    int j = lane + j0*32;
                    if (j < 34) {
                        int ww = w0 + j - 1;
                        float v = 0.f;
                        if (rok && ww >= 0 && ww < Ww) v = mp[hh*Ww + ww];
                        Xs[ci][r][j] = v;
                    }
                }
            }
        }
        __syncthreads();

        const int c = cg*8 + ci;
        float f = 0.f, d = 0.f;
#pragma unroll
        for (int tap = 0; tap < 9; tap++) {
            float xv = Xs[ci][tap/3][px + (tap%3)];
            f += fws[c][tap] * xv;
            d += dks[tap][px] * xv;
        }
        float dynv = fmaxf(d*s2a[c] + t2a[c], 0.f);
        float fixv = fmaxf(f*s1a[c] + t1a[c], 0.f);

        __nv_bfloat16 dh = __float2bfloat16(dynv);
        __nv_bfloat16 dl = __float2bfloat16(dynv - __bfloat162float(dh));
        __nv_bfloat16 fh = __float2bfloat16(fixv);
        __nv_bfloat16 fl = __float2bfloat16(fixv - __bfloat162float(fh));
        s_hi[px][c]       = dh;  s_lo[px][c]       = dl;
        s_hi[px][128 + c] = fh;  s_lo[px][128 + c] = fl;
    }
    __syncthreads();

    const int opx = tid >> 3;
    const int sub = tid & 7;
    size_t base = ((size_t)(n*HW) + (size_t)h*Ww + w0 + opx)*256 + sub*32;
    const uint4* sh = (const uint4*)&s_hi[opx][sub*32];
    const uint4* sl = (const uint4*)&s_lo[opx][sub*32];
#pragma unroll
    for (int q = 0; q < 4; q++) ((uint4*)(g_chi + base))[q] = sh[q];
#pragma unroll
    for (int q = 0; q < 4; q++) ((uint4*)(g_clo + base))[q] = sl[q];
}

// ---------------------------------------------------------------------------
// Weight prep: hi/lo bf16 split into K-chunked layouts
// ---------------------------------------------------------------------------
__global__ __launch_bounds__(256) void kw_prep(const float* __restrict__ jw)
{
    int idx = blockIdx.x * 256 + threadIdx.x;      // 18*128*64
    if (idx >= 18*128*64) return;
    int cidx = idx >> 13;
    int rr   = idx & 8191;
    int oc   = rr >> 6;
    int k    = rr & 63;
    int tap  = cidx >> 1;
    int ic   = (cidx & 1)*64 + k;
    float v = jw[oc*(Cc*9) + ic*9 + tap];
    __nv_bfloat16 hi = __float2bfloat16(v);
    __nv_bfloat16 lo = __float2bfloat16(v - __bfloat162float(hi));
    g_whi[idx] = hi;
    g_wlo[idx] = lo;
}

__global__ __launch_bounds__(256) void krw_prep(const float* __restrict__ rw)
{
    int idx = blockIdx.x * 256 + threadIdx.x;      // 4*128*64
    if (idx >= 4*128*64) return;
    int ck = idx >> 13;
    int rr = idx & 8191;
    int oc = rr >> 6;
    int k  = rr & 63;
    float v = rw[oc*256 + ck*64 + k];
    __nv_bfloat16 hi = __float2bfloat16(v);
    __nv_bfloat16 lo = __float2bfloat16(v - __bfloat162float(hi));
    g_rwhi[idx] = hi;
    g_rwlo[idx] = lo;
}

// ---------------------------------------------------------------------------
// shared GEMM smem layout (bf16 rows of 64 elems = 128B, stride 144B)
// ---------------------------------------------------------------------------
#define SA_HI 0
#define SA_LO 18432
#define SW_HI 36864
#define SW_LO 55296
#define GEMM_SMEM 73728

// ---------------------------------------------------------------------------
// K3: refine 1x1 as HMMA GEMM (K=256, 4 chunks), ldmatrix frag loads.
// Epilogue: g_fused (NCHW fp32) + p=fused+coef -> g_phi/g_plo (NHWC bf16).
// ---------------------------------------------------------------------------
__global__ __launch_bounds__(256) void k3_mma(
    const float* __restrict__ coef,
    const float* __restrict__ rb)
{
    extern __shared__ char smem[];
    __shared__ float s_rb[128];
    const int tid = threadIdx.x;
    const int wid = tid >> 5;
    const int lane = tid & 31;
    const int p0 = blockIdx.x * 128;
    const int n  = blockIdx.z;

    if (tid < 128) s_rb[tid] = rb[tid];

    const int r  = tid >> 1;
    const int hf = tid & 1;
    const int wm = (wid & 3) * 32;
    const int wn = (wid >> 2) * 64;
    const int grp = lane >> 2;
    const int t4  = lane & 3;
    const int lr = lane & 7;
    const int lg = lane >> 3;

    const uint32_t smemU = (uint32_t)__cvta_generic_to_shared(smem);
    const uint32_t aRC = (uint32_t)(wm + (lg & 1)*8 + lr)*144 + (lg >> 1)*16;
    const uint32_t bRC = (uint32_t)(wn + (lg >> 1)*8 + lr)*144 + (lg & 1)*16;

    float d[2][8][4];
#pragma unroll
    for (int mf = 0; mf < 2; mf++)
#pragma unroll
        for (int nf = 0; nf < 8; nf++)
#pragma unroll
            for (int q = 0; q < 4; q++) d[mf][nf][q] = 0.f;

    for (int ck = 0; ck < 4; ck++) {
        const uint4* pa_hi = (const uint4*)(g_chi + ((size_t)(n*HW) + p0 + r)*256 + ck*64 + hf*32);
        const uint4* pa_lo = (const uint4*)(g_clo + ((size_t)(n*HW) + p0 + r)*256 + ck*64 + hf*32);
        const uint4* pw_hi = (const uint4*)(g_rwhi + (size_t)ck*8192 + r*64 + hf*32);
        const uint4* pw_lo = (const uint4*)(g_rwlo + (size_t)ck*8192 + r*64 + hf*32);
        uint4 vah[4], val4[4], vwh[4], vwl[4];
#pragma unroll
        for (int q = 0; q < 4; q++) {
            vah[q] = pa_hi[q]; val4[q] = pa_lo[q];
            vwh[q] = pw_hi[q]; vwl[q] = pw_lo[q];
        }
        __syncthreads();
        char* dst = smem + r*144 + hf*64;
#pragma unroll
        for (int q = 0; q < 4; q++) {
            *(uint4*)(dst + SA_HI + q*16) = vah[q];
            *(uint4*)(dst + SA_LO + q*16) = val4[q];
            *(uint4*)(dst + SW_HI + q*16) = vwh[q];
            *(uint4*)(dst + SW_LO + q*16) = vwl[q];
        }
        __syncthreads();

#pragma unroll
        for (int s = 0; s < 4; s++) {
            const uint32_t kb = s*32;
            uint32_t ahi[2][4], alo[2][4];
#pragma unroll
            for (int mf = 0; mf < 2; mf++) {
                uint32_t ad = smemU + aRC + mf*(16*144) + kb;
                ldmat_x4(ahi[mf], ad + SA_HI);
                ldmat_x4(alo[mf], ad + SA_LO);
            }
#pragma unroll
            for (int p = 0; p < 4; p++) {
                uint32_t bd = smemU + bRC + p*(16*144) + kb;
                uint32_t bh[4], bl[4];
                ldmat_x4(bh, bd + SW_HI);
                ldmat_x4(bl, bd + SW_LO);
#pragma unroll
                for (int e = 0; e < 2; e++) {
                    int nf = 2*p + e;
#pragma unroll
                    for (int mf = 0; mf < 2; mf++) {
                        mma16816(d[mf][nf], ahi[mf], bh[2*e], bh[2*e+1]);
                        mma16816(d[mf][nf], ahi[mf], bl[2*e], bl[2*e+1]);
                        mma16816(d[mf][nf], alo[mf], bh[2*e], bh[2*e+1]);
                    }
                }
            }
        }
    }

    __syncthreads();
    float* sD = (float*)smem;    // [128 oc][132 px]
#pragma unroll
    for (int mf = 0; mf < 2; mf++)
#pragma unroll
        for (int nf = 0; nf < 8; nf++) {
            int row = wm + mf*16 + grp;
            int col = wn + nf*8 + 2*t4;
            sD[(col  )*132 + row    ] = d[mf][nf][0];
            sD[(col+1)*132 + row    ] = d[mf][nf][1];
            sD[(col  )*132 + row + 8] = d[mf][nf][2];
            sD[(col+1)*132 + row + 8] = d[mf][nf][3];
        }
    __syncthreads();

    const size_t nplane = (size_t)n*Cc*HW;

    // pass 1: fused (NCHW fp32, coalesced)
    {
        const int pxq = (tid & 31) * 4;
#pragma unroll 2
        for (int j = 0; j < 16; j++) {
            int oc = (tid >> 5) + j*8;
            float4 a4 = *(const float4*)&sD[oc*132 + pxq];
            float b = s_rb[oc];
            float4 o = make_float4(a4.x + b, a4.y + b, a4.z + b, a4.w + b);
            *(float4*)(g_fused + nplane + (size_t)oc*HW + p0 + pxq) = o;
        }
    }

    // pass 2: p = fused + coef -> NHWC bf16 hi/lo
    {
        const int px2 = tid >> 1;
        const int half = tid & 1;
#pragma unroll
        for (int jj = 0; jj < 16; jj++) {
            __nv_bfloat16 hv[4], lv[4];
#pragma unroll
            for (int e = 0; e < 4; e++) {
                int oc = half*64 + jj*4 + e;
                float v = sD[oc*132 + px2] + s_rb[oc]
                        + coef[nplane + (size_t)oc*HW + p0 + px2];
                hv[e] = __float2bfloat16(v);
                lv[e] = __float2bfloat16(v - __bfloat162float(hv[e]));
            }
            size_t dst = ((size_t)(n*HW) + p0 + px2)*128 + half*64 + jj*4;
            *(uint2*)(g_phi + dst) = make_uint2(pack_bf2(hv[0],hv[1]), pack_bf2(hv[2],hv[3]));
            *(uint2*)(g_plo + dst) = make_uint2(pack_bf2(lv[0],lv[1]), pack_bf2(lv[2],lv[3]));
        }
    }
}

// ---------------------------------------------------------------------------
// K4: joint 3x3 conv as HMMA implicit GEMM (ldmatrix) + gating epilogue.
// ---------------------------------------------------------------------------
__global__ __launch_bounds__(256) void k4_wmma(
    const float* __restrict__ coef,
    const float* __restrict__ jb,
    float* __restrict__ out)
{
    extern __shared__ char smem[];
    const int tid = threadIdx.x;
    const int wid = tid >> 5;
    const int lane = tid & 31;
    const int w0 = blockIdx.x * 128;
    const int h  = blockIdx.y;
    const int n  = blockIdx.z;

    const int r  = tid >> 1;
    const int hf = tid & 1;
    const int wm = (wid & 3) * 32;
    const int wn = (wid >> 2) * 64;
    const int grp = lane >> 2;
    const int t4  = lane & 3;
    const int lr = lane & 7;
    const int lg = lane >> 3;

    const uint32_t smemU = (uint32_t)__cvta_generic_to_shared(smem);
    const uint32_t aRC = (uint32_t)(wm + (lg & 1)*8 + lr)*144 + (lg >> 1)*16;
    const uint32_t bRC = (uint32_t)(wn + (lg >> 1)*8 + lr)*144 + (lg & 1)*16;

    float d[2][8][4];
#pragma unroll
    for (int mf = 0; mf < 2; mf++)
#pragma unroll
        for (int nf = 0; nf < 8; nf++)
#pragma unroll
            for (int q = 0; q < 4; q++) d[mf][nf][q] = 0.f;

    const uint4 z4 = make_uint4(0,0,0,0);

    for (int cidx = 0; cidx < 18; cidx++) {
        const int tap = cidx >> 1;
        const int hk  = cidx & 1;
        const int dy = tap / 3, dx = tap % 3;
        const int hh = h + dy - 1;
        const int ww = w0 + dx - 1 + r;
        const bool val = (hh >= 0 && hh < Hh && ww >= 0 && ww < Ww);

        const size_t pix = (size_t)n*HW + (size_t)hh*Ww + ww;
        const uint4* pa_hi = (const uint4*)(g_phi + pix*Cc + hk*64 + hf*32);
        const uint4* pa_lo = (const uint4*)(g_plo + pix*Cc + hk*64 + hf*32);
        const uint4* pw_hi = (const uint4*)(g_whi + (size_t)cidx*8192 + r*64 + hf*32);
        const uint4* pw_lo = (const uint4*)(g_wlo + (size_t)cidx*8192 + r*64 + hf*32);
        uint4 vah[4], val4[4], vwh[4], vwl[4];
#pragma unroll
        for (int q = 0; q < 4; q++) {
            vah[q] = val ? pa_hi[q] : z4;
            val4[q] = val ? pa_lo[q] : z4;
            vwh[q] = pw_hi[q];
            vwl[q] = pw_lo[q];
        }

        __syncthreads();
        char* dst = smem + r*144 + hf*64;
#pragma unroll
        for (int q = 0; q < 4; q++) {
            *(uint4*)(dst + SA_HI + q*16) = vah[q];
            *(uint4*)(dst + SA_LO + q*16) = val4[q];
            *(uint4*)(dst + SW_HI + q*16) = vwh[q];
            *(uint4*)(dst + SW_LO + q*16) = vwl[q];
        }
        __syncthreads();

#pragma unroll
        for (int s = 0; s < 4; s++) {
            const uint32_t kb = s*32;
            uint32_t ahi[2][4], alo[2][4];
#pragma unroll
            for (int mf = 0; mf < 2; mf++) {
                uint32_t ad = smemU + aRC + mf*(16*144) + kb;
                ldmat_x4(ahi[mf], ad + SA_HI);
                ldmat_x4(alo[mf], ad + SA_LO);
            }
#pragma unroll
            for (int p = 0; p < 4; p++) {
                uint32_t bd = smemU + bRC + p*(16*144) + kb;
                uint32_t bh[4], bl[4];
                ldmat_x4(bh, bd + SW_HI);
                ldmat_x4(bl, bd + SW_LO);
#pragma unroll
                for (int e = 0; e < 2; e++) {
                    int nf = 2*p + e;
#pragma unroll
                    for (int mf = 0; mf < 2; mf++) {
                        mma16816(d[mf][nf], ahi[mf], bh[2*e], bh[2*e+1]);
                        mma16816(d[mf][nf], ahi[mf], bl[2*e], bl[2*e+1]);
                        mma16816(d[mf][nf], alo[mf], bh[2*e], bh[2*e+1]);
                    }
                }
            }
        }
    }

    __syncthreads();
    float* sD = (float*)smem;
#pragma unroll
    for (int mf = 0; mf < 2; mf++)
#pragma unroll
        for (int nf = 0; nf < 8; nf++) {
            int row = wm + mf*16 + grp;
            int col = wn + nf*8 + 2*t4;
            sD[(col  )*132 + row    ] = d[mf][nf][0];
            sD[(col+1)*132 + row    ] = d[mf][nf][1];
            sD[(col  )*132 + row + 8] = d[mf][nf][2];
            sD[(col+1)*132 + row + 8] = d[mf][nf][3];
        }
    __syncthreads();

    const size_t nplane = (size_t)n*Cc*HW;
    const int px = (tid & 31) * 4;
#pragma unroll 2
    for (int j = 0; j < 16; j++) {
        int oc = (tid >> 5) + j*8;
        float4 a4 = *(const float4*)&sD[oc*132 + px];
        float b = jb[oc];
        size_t base = nplane + (size_t)oc*HW + (size_t)h*Ww + w0 + px;
        float4 fu = *(const float4*)&g_fused[base];
        float4 cf = *(const float4*)&coef[base];
        float4 o;
        { float p2 = 1.f/(1.f + __expf(-(a4.x + b))); o.x = fu.x + p2*(cf.x - fu.x); }
        { float p2 = 1.f/(1.f + __expf(-(a4.y + b))); o.y = fu.y + p2*(cf.y - fu.y); }
        { float p2 = 1.f/(1.f + __expf(-(a4.z + b))); o.z = fu.z + p2*(cf.z - fu.z); }
        { float p2 = 1.f/(1.f + __expf(-(a4.w + b))); o.w = fu.w + p2*(cf.w - fu.w); }
        *(float4*)(out + base) = o;
    }
}

// ---------------------------------------------------------------------------
extern "C" void kernel_launch(void* const* d_in, const int* in_sizes, int n_in,
                              void* d_out, int out_size)
{
    const float* coef  = (const float*)d_in[0];
    const float* ms    = (const float*)d_in[1];
    const float* fix_w = (const float*)d_in[2];
    const float* bn1_g = (const float*)d_in[3];
    const float* bn1_b = (const float*)d_in[4];
    const float* bn1_m = (const float*)d_in[5];
    const float* bn1_v = (const float*)d_in[6];
    const float* dyn_w = (const float*)d_in[7];
    const float* dyn_b = (const float*)d_in[8];
    const float* bn2_g = (const float*)d_in[9];
    const float* bn2_b = (const float*)d_in[10];
    const float* bn2_m = (const float*)d_in[11];
    const float* bn2_v = (const float*)d_in[12];
    const float* refine_w = (const float*)d_in[13];
    const float* refine_b = (const float*)d_in[14];
    const float* joint_w  = (const float*)d_in[15];
    const float* joint_b  = (const float*)d_in[16];
    float* outp = (float*)d_out;

    cudaFuncSetAttribute(k3_mma,  cudaFuncAttributeMaxDynamicSharedMemorySize, GEMM_SMEM);
    cudaFuncSetAttribute(k4_wmma, cudaFuncAttributeMaxDynamicSharedMemorySize, GEMM_SMEM);

    kw_prep<<<(18*128*64 + 255)/256, 256>>>(joint_w);
    krw_prep<<<(4*128*64 + 255)/256, 256>>>(refine_w);
    k1_dynkernel<<<dim3(Ww/128, Hh, Nn), 128>>>(ms, dyn_w, dyn_b);
    k2_cat_nhwc<<<dim3(Ww/32, Hh, Nn), 256>>>(ms, fix_w,
                                              bn1_g, bn1_b, bn1_m, bn1_v,
                                              bn2_g, bn2_b, bn2_m, bn2_v);
    k3_mma<<<dim3(HW/128, 1, Nn), 256, GEMM_SMEM>>>(coef, refine_b);
    k4_wmma<<<dim3(Ww/128, Hh, Nn), 256, GEMM_SMEM>>>(coef, joint_b, outp);
}

// round 6
// speedup vs baseline: 1.9697x; 1.0842x over previous
#include <cuda_runtime.h>
#include <cuda_bf16.h>
#include <cstdint>

#define Nn 4
#define Cc 128
#define Hh 256
#define Ww 256
#define HW (Hh*Ww)

// ---------------- scratch (device globals; allocation-free) ----------------
__device__ float g_dk[(size_t)Nn*9*HW];                            // dyn kernels
__device__ float g_fused[(size_t)Nn*Cc*HW];                        // refine out NCHW
__device__ __align__(256) __nv_bfloat16 g_chi[(size_t)Nn*HW*256];  // cat NHWC hi
__device__ __align__(256) __nv_bfloat16 g_clo[(size_t)Nn*HW*256];  // cat NHWC lo
__device__ __align__(256) __nv_bfloat16 g_phi[(size_t)Nn*HW*Cc];   // p NHWC hi
__device__ __align__(256) __nv_bfloat16 g_plo[(size_t)Nn*HW*Cc];   // p NHWC lo
__device__ __align__(256) __nv_bfloat16 g_whi[18*128*64];          // joint W hi
__device__ __align__(256) __nv_bfloat16 g_wlo[18*128*64];          // joint W lo
__device__ __align__(256) __nv_bfloat16 g_rwhi[4*128*64];          // refine W hi
__device__ __align__(256) __nv_bfloat16 g_rwlo[4*128*64];          // refine W lo

// ---------------------------------------------------------------------------
__device__ __forceinline__ void mma16816(float* d, const uint32_t* a,
                                         uint32_t b0, uint32_t b1) {
    asm volatile(
        "mma.sync.aligned.m16n8k16.row.col.f32.bf16.bf16.f32 "
        "{%0,%1,%2,%3}, {%4,%5,%6,%7}, {%8,%9}, {%0,%1,%2,%3};"
        : "+f"(d[0]), "+f"(d[1]), "+f"(d[2]), "+f"(d[3])
        : "r"(a[0]), "r"(a[1]), "r"(a[2]), "r"(a[3]), "r"(b0), "r"(b1));
}
__device__ __forceinline__ void ldmat_x4(uint32_t* r, uint32_t saddr) {
    asm volatile("ldmatrix.sync.aligned.m8n8.x4.shared.b16 {%0,%1,%2,%3}, [%4];"
        : "=r"(r[0]), "=r"(r[1]), "=r"(r[2]), "=r"(r[3]) : "r"(saddr));
}
__device__ __forceinline__ uint32_t pack_bf2(__nv_bfloat16 a, __nv_bfloat16 b) {
    __nv_bfloat162 h2; h2.x = a; h2.y = b;
    return *(uint32_t*)&h2;
}

// ---------------------------------------------------------------------------
// K1: dyn_kernel conv(ms, dyn_w[9,128,3,3]) + b, L1-normalized over 9 taps
// ---------------------------------------------------------------------------
__global__ __launch_bounds__(128) void k1_dynkernel(
    const float* __restrict__ ms,
    const float* __restrict__ dyn_w,
    const float* __restrict__ dyn_b)
{
    const int w0 = blockIdx.x * 128;
    const int h  = blockIdx.y;
    const int n  = blockIdx.z;
    const int tid = threadIdx.x;

    __shared__ float Xs[3][130];
    __shared__ float Wsm[9][9];

    float acc[9];
#pragma unroll
    for (int k = 0; k < 9; k++) acc[k] = dyn_b[k];

    for (int ic = 0; ic < Cc; ic++) {
        const float* mp = ms + ((size_t)(n*Cc + ic))*HW;
        for (int idx = tid; idx < 3*130; idx += 128) {
            int r = idx / 130, cc2 = idx % 130;
            int hh = h + r - 1, ww = w0 + cc2 - 1;
            float v = 0.f;
            if (hh >= 0 && hh < Hh && ww >= 0 && ww < Ww) v = mp[hh*Ww + ww];
            Xs[r][cc2] = v;
        }
        if (tid < 81)
            Wsm[tid/9][tid%9] = dyn_w[(tid/9)*(Cc*9) + ic*9 + (tid%9)];
        __syncthreads();

#pragma unroll
        for (int tap = 0; tap < 9; tap++) {
            float xv = Xs[tap/3][tid + (tap%3)];
#pragma unroll
            for (int k = 0; k < 9; k++) acc[k] += Wsm[k][tap] * xv;
        }
        __syncthreads();
    }

    float denom = 0.f;
#pragma unroll
    for (int k = 0; k < 9; k++) denom += fabsf(acc[k]);
    float inv = 1.f / denom;
#pragma unroll
    for (int k = 0; k < 9; k++)
        g_dk[((size_t)(n*9 + k))*HW + (size_t)h*Ww + w0 + tid] = acc[k] * inv;
}

// ---------------------------------------------------------------------------
// K2: concat tensor in NHWC bf16 hi/lo. Warp-private tiles: no block
// barriers inside the channel loop (only __syncwarp).
// ---------------------------------------------------------------------------
__global__ __launch_bounds__(256) void k2_cat_nhwc(
    const float* __restrict__ ms,
    const float* __restrict__ fix_w,
    const float* __restrict__ bn1_g, const float* __restrict__ bn1_b,
    const float* __restrict__ bn1_m, const float* __restrict__ bn1_v,
    const float* __restrict__ bn2_g, const float* __restrict__ bn2_b,
    const float* __restrict__ bn2_m, const float* __restrict__ bn2_v)
{
    const int w0 = blockIdx.x * 32;
    const int h  = blockIdx.y;
    const int n  = blockIdx.z;
    const int tid = threadIdx.x;
    const int lane = tid & 31;

    __shared__ float dks[9][32];
    __shared__ float Xs[8][3][34];
    __shared__ float s1a[128], t1a[128], s2a[128], t2a[128];
    __shared__ float fws[128][10];
    __shared__ __nv_bfloat16 s_hi[32][264];
    __shared__ __nv_bfloat16 s_lo[32][264];

    if (tid < 128) {
        float s1 = bn1_g[tid] * rsqrtf(bn1_v[tid] + 1e-5f);
        s1a[tid] = s1; t1a[tid] = bn1_b[tid] - bn1_m[tid]*s1;
        float s2 = bn2_g[tid] * rsqrtf(bn2_v[tid] + 1e-5f);
        s2a[tid] = s2; t2a[tid] = bn2_b[tid] - bn2_m[tid]*s2;
    }
    for (int idx = tid; idx < 1152; idx += 256)
        fws[idx/9][idx%9] = fix_w[idx];
    for (int idx = tid; idx < 288; idx += 256) {
        int tap = idx >> 5, px = idx & 31;
        dks[tap][px] = g_dk[((size_t)(n*9 + tap))*HW + (size_t)h*Ww + w0 + px];
    }
    __syncthreads();

    const int ci = tid >> 5;
    const int px = lane;

    for (int cg = 0; cg < 16; cg++) {
        const int c = cg*8 + ci;
        {
            const float* mp = ms + ((size_t)(n*Cc + c))*HW;
#pragma unroll
            for (int r = 0; r < 3; r++) {
                int hh = h + r - 1;
                bool rok = (hh >= 0 && hh < Hh);
#pragma unroll
                for (int j0 = 0; j0 < 2; j0++) {
                    int j = lane + j0*32;
                    if (j < 34) {
                        int ww = w0 + j - 1;
                        float v = 0.f;
                        if (rok && ww >= 0 && ww < Ww) v = mp[hh*Ww + ww];
                        Xs[ci][r][j] = v;
                    }
                }
            }
        }
        __syncwarp();

        float f = 0.f, d = 0.f;
#pragma unroll
        for (int tap = 0; tap < 9; tap++) {
            float xv = Xs[ci][tap/3][px + (tap%3)];
            f += fws[c][tap] * xv;
            d += dks[tap][px] * xv;
        }
        float dynv = fmaxf(d*s2a[c] + t2a[c], 0.f);
        float fixv = fmaxf(f*s1a[c] + t1a[c], 0.f);

        __nv_bfloat16 dh = __float2bfloat16(dynv);
        __nv_bfloat16 dl = __float2bfloat16(dynv - __bfloat162float(dh));
        __nv_bfloat16 fh = __float2bfloat16(fixv);
        __nv_bfloat16 fl = __float2bfloat16(fixv - __bfloat162float(fh));
        s_hi[px][c]       = dh;  s_lo[px][c]       = dl;
        s_hi[px][128 + c] = fh;  s_lo[px][128 + c] = fl;
        __syncwarp();   // Xs[ci] reads done before next iteration overwrites
    }
    __syncthreads();

    const int opx = tid >> 3;
    const int sub = tid & 7;
    size_t base = ((size_t)(n*HW) + (size_t)h*Ww + w0 + opx)*256 + sub*32;
    const uint4* sh = (const uint4*)&s_hi[opx][sub*32];
    const uint4* sl = (const uint4*)&s_lo[opx][sub*32];
#pragma unroll
    for (int q = 0; q < 4; q++) ((uint4*)(g_chi + base))[q] = sh[q];
#pragma unroll
    for (int q = 0; q < 4; q++) ((uint4*)(g_clo + base))[q] = sl[q];
}

// ---------------------------------------------------------------------------
// Weight prep: hi/lo bf16 split into K-chunked layouts
// ---------------------------------------------------------------------------
__global__ __launch_bounds__(256) void kw_prep(const float* __restrict__ jw)
{
    int idx = blockIdx.x * 256 + threadIdx.x;      // 18*128*64
    if (idx >= 18*128*64) return;
    int cidx = idx >> 13;
    int rr   = idx & 8191;
    int oc   = rr >> 6;
    int k    = rr & 63;
    int tap  = cidx >> 1;
    int ic   = (cidx & 1)*64 + k;
    float v = jw[oc*(Cc*9) + ic*9 + tap];
    __nv_bfloat16 hi = __float2bfloat16(v);
    __nv_bfloat16 lo = __float2bfloat16(v - __bfloat162float(hi));
    g_whi[idx] = hi;
    g_wlo[idx] = lo;
}

__global__ __launch_bounds__(256) void krw_prep(const float* __restrict__ rw)
{
    int idx = blockIdx.x * 256 + threadIdx.x;      // 4*128*64
    if (idx >= 4*128*64) return;
    int ck = idx >> 13;
    int rr = idx & 8191;
    int oc = rr >> 6;
    int k  = rr & 63;
    float v = rw[oc*256 + ck*64 + k];
    __nv_bfloat16 hi = __float2bfloat16(v);
    __nv_bfloat16 lo = __float2bfloat16(v - __bfloat162float(hi));
    g_rwhi[idx] = hi;
    g_rwlo[idx] = lo;
}

// ---------------------------------------------------------------------------
// shared GEMM smem layout (bf16 rows of 64 elems = 128B, stride 144B)
// ---------------------------------------------------------------------------
#define SA_HI 0
#define SA_LO 18432
#define SW_HI 36864
#define SW_LO 55296
#define GEMM_SMEM 73728

// ---------------------------------------------------------------------------
// K3: refine 1x1 as HMMA GEMM (K=256, 4 chunks), ldmatrix + prefetch.
// Epilogue: g_fused (NCHW fp32) + p=fused+coef -> g_phi/g_plo (NHWC bf16).
// ---------------------------------------------------------------------------
__global__ __launch_bounds__(256) void k3_mma(
    const float* __restrict__ coef,
    const float* __restrict__ rb)
{
    extern __shared__ char smem[];
    __shared__ float s_rb[128];
    const int tid = threadIdx.x;
    const int wid = tid >> 5;
    const int lane = tid & 31;
    const int p0 = blockIdx.x * 128;
    const int n  = blockIdx.z;

    if (tid < 128) s_rb[tid] = rb[tid];

    const int r  = tid >> 1;
    const int hf = tid & 1;
    const int wm = (wid & 3) * 32;
    const int wn = (wid >> 2) * 64;
    const int grp = lane >> 2;
    const int t4  = lane & 3;
    const int lr = lane & 7;
    const int lg = lane >> 3;

    const uint32_t smemU = (uint32_t)__cvta_generic_to_shared(smem);
    const uint32_t aRC = (uint32_t)(wm + (lg & 1)*8 + lr)*144 + (lg >> 1)*16;
    const uint32_t bRC = (uint32_t)(wn + (lg >> 1)*8 + lr)*144 + (lg & 1)*16;

    float d[2][8][4];
#pragma unroll
    for (int mf = 0; mf < 2; mf++)
#pragma unroll
        for (int nf = 0; nf < 8; nf++)
#pragma unroll
            for (int q = 0; q < 4; q++) d[mf][nf][q] = 0.f;

    uint4 vah[4], val4[4], vwh[4], vwl[4];
    // prologue: load chunk 0
    {
        const uint4* pa_hi = (const uint4*)(g_chi + ((size_t)(n*HW) + p0 + r)*256 + hf*32);
        const uint4* pa_lo = (const uint4*)(g_clo + ((size_t)(n*HW) + p0 + r)*256 + hf*32);
        const uint4* pw_hi = (const uint4*)(g_rwhi + (size_t)r*64 + hf*32);
        const uint4* pw_lo = (const uint4*)(g_rwlo + (size_t)r*64 + hf*32);
#pragma unroll
        for (int q = 0; q < 4; q++) {
            vah[q] = pa_hi[q]; val4[q] = pa_lo[q];
            vwh[q] = pw_hi[q]; vwl[q] = pw_lo[q];
        }
    }

    for (int ck = 0; ck < 4; ck++) {
        __syncthreads();
        char* dst = smem + r*144 + hf*64;
#pragma unroll
        for (int q = 0; q < 4; q++) {
            *(uint4*)(dst + SA_HI + q*16) = vah[q];
            *(uint4*)(dst + SA_LO + q*16) = val4[q];
            *(uint4*)(dst + SW_HI + q*16) = vwh[q];
            *(uint4*)(dst + SW_LO + q*16) = vwl[q];
        }
        __syncthreads();

        if (ck + 1 < 4) {   // prefetch next chunk (overlaps MMAs below)
            const uint4* pa_hi = (const uint4*)(g_chi + ((size_t)(n*HW) + p0 + r)*256 + (ck+1)*64 + hf*32);
            const uint4* pa_lo = (const uint4*)(g_clo + ((size_t)(n*HW) + p0 + r)*256 + (ck+1)*64 + hf*32);
            const uint4* pw_hi = (const uint4*)(g_rwhi + (size_t)(ck+1)*8192 + r*64 + hf*32);
            const uint4* pw_lo = (const uint4*)(g_rwlo + (size_t)(ck+1)*8192 + r*64 + hf*32);
#pragma unroll
            for (int q = 0; q < 4; q++) {
                vah[q] = pa_hi[q]; val4[q] = pa_lo[q];
                vwh[q] = pw_hi[q]; vwl[q] = pw_lo[q];
            }
        }

#pragma unroll
        for (int s = 0; s < 4; s++) {
            const uint32_t kb = s*32;
            uint32_t ahi[2][4], alo[2][4];
#pragma unroll
            for (int mf = 0; mf < 2; mf++) {
                uint32_t ad = smemU + aRC + mf*(16*144) + kb;
                ldmat_x4(ahi[mf], ad + SA_HI);
                ldmat_x4(alo[mf], ad + SA_LO);
            }
#pragma unroll
            for (int p = 0; p < 4; p++) {
                uint32_t bd = smemU + bRC + p*(16*144) + kb;
                uint32_t bh[4], bl[4];
                ldmat_x4(bh, bd + SW_HI);
                ldmat_x4(bl, bd + SW_LO);
#pragma unroll
                for (int e = 0; e < 2; e++) {
                    int nf = 2*p + e;
#pragma unroll
                    for (int mf = 0; mf < 2; mf++) {
                        mma16816(d[mf][nf], ahi[mf], bh[2*e], bh[2*e+1]);
                        mma16816(d[mf][nf], ahi[mf], bl[2*e], bl[2*e+1]);
                        mma16816(d[mf][nf], alo[mf], bh[2*e], bh[2*e+1]);
                    }
                }
            }
        }
    }

    __syncthreads();
    float* sD = (float*)smem;    // [128 oc][132 px]
#pragma unroll
    for (int mf = 0; mf < 2; mf++)
#pragma unroll
        for (int nf = 0; nf < 8; nf++) {
            int row = wm + mf*16 + grp;
            int col = wn + nf*8 + 2*t4;
            sD[(col  )*132 + row    ] = d[mf][nf][0];
            sD[(col+1)*132 + row    ] = d[mf][nf][1];
            sD[(col  )*132 + row + 8] = d[mf][nf][2];
            sD[(col+1)*132 + row + 8] = d[mf][nf][3];
        }
    __syncthreads();

    const size_t nplane = (size_t)n*Cc*HW;

    // pass 1: fused (NCHW fp32, coalesced)
    {
        const int pxq = (tid & 31) * 4;
#pragma unroll 2
        for (int j = 0; j < 16; j++) {
            int oc = (tid >> 5) + j*8;
            float4 a4 = *(const float4*)&sD[oc*132 + pxq];
            float b = s_rb[oc];
            float4 o = make_float4(a4.x + b, a4.y + b, a4.z + b, a4.w + b);
            *(float4*)(g_fused + nplane + (size_t)oc*HW + p0 + pxq) = o;
        }
    }

    // pass 2: p = fused + coef -> NHWC bf16 hi/lo
    {
        const int px2 = tid >> 1;
        const int half = tid & 1;
#pragma unroll
        for (int jj = 0; jj < 16; jj++) {
            __nv_bfloat16 hv[4], lv[4];
#pragma unroll
            for (int e = 0; e < 4; e++) {
                int oc = half*64 + jj*4 + e;
                float v = sD[oc*132 + px2] + s_rb[oc]
                        + coef[nplane + (size_t)oc*HW + p0 + px2];
                hv[e] = __float2bfloat16(v);
                lv[e] = __float2bfloat16(v - __bfloat162float(hv[e]));
            }
            size_t dst = ((size_t)(n*HW) + p0 + px2)*128 + half*64 + jj*4;
            *(uint2*)(g_phi + dst) = make_uint2(pack_bf2(hv[0],hv[1]), pack_bf2(hv[2],hv[3]));
            *(uint2*)(g_plo + dst) = make_uint2(pack_bf2(lv[0],lv[1]), pack_bf2(lv[2],lv[3]));
        }
    }
}

// ---------------------------------------------------------------------------
// K4: joint 3x3 conv as HMMA implicit GEMM (ldmatrix + prefetch) + gating.
// ---------------------------------------------------------------------------
__global__ __launch_bounds__(256) void k4_wmma(
    const float* __restrict__ coef,
    const float* __restrict__ jb,
    float* __restrict__ out)
{
    extern __shared__ char smem[];
    const int tid = threadIdx.x;
    const int wid = tid >> 5;
    const int lane = tid & 31;
    const int w0 = blockIdx.x * 128;
    const int h  = blockIdx.y;
    const int n  = blockIdx.z;

    const int r  = tid >> 1;
    const int hf = tid & 1;
    const int wm = (wid & 3) * 32;
    const int wn = (wid >> 2) * 64;
    const int grp = lane >> 2;
    const int t4  = lane & 3;
    const int lr = lane & 7;
    const int lg = lane >> 3;

    const uint32_t smemU = (uint32_t)__cvta_generic_to_shared(smem);
    const uint32_t aRC = (uint32_t)(wm + (lg & 1)*8 + lr)*144 + (lg >> 1)*16;
    const uint32_t bRC = (uint32_t)(wn + (lg >> 1)*8 + lr)*144 + (lg & 1)*16;

    float d[2][8][4];
#pragma unroll
    for (int mf = 0; mf < 2; mf++)
#pragma unroll
        for (int nf = 0; nf < 8; nf++)
#pragma unroll
            for (int q = 0; q < 4; q++) d[mf][nf][q] = 0.f;

    const uint4 z4 = make_uint4(0,0,0,0);
    uint4 vah[4], val4[4], vwh[4], vwl[4];

    // chunk loader into regs
    auto loadChunk = [&](int cidx) {
        const int tap = cidx >> 1;
        const int hk  = cidx & 1;
        const int dy = tap / 3, dx = tap % 3;
        const int hh = h + dy - 1;
        const int ww = w0 + dx - 1 + r;
        const bool val = (hh >= 0 && hh < Hh && ww >= 0 && ww < Ww);
        const size_t pix = (size_t)n*HW + (size_t)hh*Ww + ww;
        const uint4* pa_hi = (const uint4*)(g_phi + pix*Cc + hk*64 + hf*32);
        const uint4* pa_lo = (const uint4*)(g_plo + pix*Cc + hk*64 + hf*32);
        const uint4* pw_hi = (const uint4*)(g_whi + (size_t)cidx*8192 + r*64 + hf*32);
        const uint4* pw_lo = (const uint4*)(g_wlo + (size_t)cidx*8192 + r*64 + hf*32);
#pragma unroll
        for (int q = 0; q < 4; q++) {
            vah[q] = val ? pa_hi[q] : z4;
            val4[q] = val ? pa_lo[q] : z4;
            vwh[q] = pw_hi[q];
            vwl[q] = pw_lo[q];
        }
    };

    loadChunk(0);

    for (int cidx = 0; cidx < 18; cidx++) {
        __syncthreads();
        char* dst = smem + r*144 + hf*64;
#pragma unroll
        for (int q = 0; q < 4; q++) {
            *(uint4*)(dst + SA_HI + q*16) = vah[q];
            *(uint4*)(dst + SA_LO + q*16) = val4[q];
            *(uint4*)(dst + SW_HI + q*16) = vwh[q];
            *(uint4*)(dst + SW_LO + q*16) = vwl[q];
        }
        __syncthreads();

        if (cidx + 1 < 18) loadChunk(cidx + 1);   // overlaps MMAs below

#pragma unroll
        for (int s = 0; s < 4; s++) {
            const uint32_t kb = s*32;
            uint32_t ahi[2][4], alo[2][4];
#pragma unroll
            for (int mf = 0; mf < 2; mf++) {
                uint32_t ad = smemU + aRC + mf*(16*144) + kb;
                ldmat_x4(ahi[mf], ad + SA_HI);
                ldmat_x4(alo[mf], ad + SA_LO);
            }
#pragma unroll
            for (int p = 0; p < 4; p++) {
                uint32_t bd = smemU + bRC + p*(16*144) + kb;
                uint32_t bh[4], bl[4];
                ldmat_x4(bh, bd + SW_HI);
                ldmat_x4(bl, bd + SW_LO);
#pragma unroll
                for (int e = 0; e < 2; e++) {
                    int nf = 2*p + e;
#pragma unroll
                    for (int mf = 0; mf < 2; mf++) {
                        mma16816(d[mf][nf], ahi[mf], bh[2*e], bh[2*e+1]);
                        mma16816(d[mf][nf], ahi[mf], bl[2*e], bl[2*e+1]);
                        mma16816(d[mf][nf], alo[mf], bh[2*e], bh[2*e+1]);
                    }
                }
            }
        }
    }

    __syncthreads();
    float* sD = (float*)smem;
#pragma unroll
    for (int mf = 0; mf < 2; mf++)
#pragma unroll
        for (int nf = 0; nf < 8; nf++) {
            int row = wm + mf*16 + grp;
            int col = wn + nf*8 + 2*t4;
            sD[(col  )*132 + row    ] = d[mf][nf][0];
            sD[(col+1)*132 + row    ] = d[mf][nf][1];
            sD[(col  )*132 + row + 8] = d[mf][nf][2];
            sD[(col+1)*132 + row + 8] = d[mf][nf][3];
        }
    __syncthreads();

    const size_t nplane = (size_t)n*Cc*HW;
    const int px = (tid & 31) * 4;
#pragma unroll 2
    for (int j = 0; j < 16; j++) {
        int oc = (tid >> 5) + j*8;
        float4 a4 = *(const float4*)&sD[oc*132 + px];
        float b = jb[oc];
        size_t base = nplane + (size_t)oc*HW + (size_t)h*Ww + w0 + px;
        float4 fu = *(const float4*)&g_fused[base];
        float4 cf = *(const float4*)&coef[base];
        float4 o;
        { float p2 = 1.f/(1.f + __expf(-(a4.x + b))); o.x = fu.x + p2*(cf.x - fu.x); }
        { float p2 = 1.f/(1.f + __expf(-(a4.y + b))); o.y = fu.y + p2*(cf.y - fu.y); }
        { float p2 = 1.f/(1.f + __expf(-(a4.z + b))); o.z = fu.z + p2*(cf.z - fu.z); }
        { float p2 = 1.f/(1.f + __expf(-(a4.w + b))); o.w = fu.w + p2*(cf.w - fu.w); }
        *(float4*)(out + base) = o;
    }
}

// ---------------------------------------------------------------------------
extern "C" void kernel_launch(void* const* d_in, const int* in_sizes, int n_in,
                              void* d_out, int out_size)
{
    const float* coef  = (const float*)d_in[0];
    const float* ms    = (const float*)d_in[1];
    const float* fix_w = (const float*)d_in[2];
    const float* bn1_g = (const float*)d_in[3];
    const float* bn1_b = (const float*)d_in[4];
    const float* bn1_m = (const float*)d_in[5];
    const float* bn1_v = (const float*)d_in[6];
    const float* dyn_w = (const float*)d_in[7];
    const float* dyn_b = (const float*)d_in[8];
    const float* bn2_g = (const float*)d_in[9];
    const float* bn2_b = (const float*)d_in[10];
    const float* bn2_m = (const float*)d_in[11];
    const float* bn2_v = (const float*)d_in[12];
    const float* refine_w = (const float*)d_in[13];
    const float* refine_b = (const float*)d_in[14];
    const float* joint_w  = (const float*)d_in[15];
    const float* joint_b  = (const float*)d_in[16];
    float* outp = (float*)d_out;

    cudaFuncSetAttribute(k3_mma,  cudaFuncAttributeMaxDynamicSharedMemorySize, GEMM_SMEM);
    cudaFuncSetAttribute(k4_wmma, cudaFuncAttributeMaxDynamicSharedMemorySize, GEMM_SMEM);

    kw_prep<<<(18*128*64 + 255)/256, 256>>>(joint_w);
    krw_prep<<<(4*128*64 + 255)/256, 256>>>(refine_w);
    k1_dynkernel<<<dim3(Ww/128, Hh, Nn), 128>>>(ms, dyn_w, dyn_b);
    k2_cat_nhwc<<<dim3(Ww/32, Hh, Nn), 256>>>(ms, fix_w,
                                              bn1_g, bn1_b, bn1_m, bn1_v,
                                              bn2_g, bn2_b, bn2_m, bn2_v);
    k3_mma<<<dim3(HW/128, 1, Nn), 256, GEMM_SMEM>>>(coef, refine_b);
    k4_wmma<<<dim3(Ww/128, Hh, Nn), 256, GEMM_SMEM>>>(coef, joint_b, outp);
}